// round 4
// baseline (speedup 1.0000x reference)
#include <cuda_runtime.h>
#include <math.h>

#define BT   2048     // B*T
#define DM   1024     // d_model
#define NH   16
#define DKV  64
#define DFF  2736
#define NC   16       // chunks per sequence (T=1024 / 64)
#define CS   64       // chunk size
#define NBHC 512      // B*H*NC = 2*16*16
#define PAD  68       // smem row stride (floats): 16B-aligned + bank skew

typedef unsigned long long u64;

// ---------------- scratch (static device globals; no allocation) ----------------
__device__ float g_h [BT*DM];
__device__ float g_q [BT*DM];
__device__ float g_k [BT*DM];
__device__ float g_v [BT*DM];
__device__ float g_a [BT*DM];
__device__ float g_o [BT*DM];
__device__ float g_x1[BT*DM];
__device__ float g_f1[BT*DFF];
__device__ float g_f2[BT*DFF];
__device__ float g_P [NBHC*4096];   // per-chunk summary [dk,dv]
__device__ float g_Ss[NBHC*4096];   // state BEFORE each chunk [dk,dv]
__device__ float g_Ae[NBHC*64];     // per-chunk full gate product per dk-dim

// ---------------- RMSNorm: one block per row of 1024 ----------------
__global__ void rmsnorm_kernel(const float* __restrict__ x,
                               const float* __restrict__ g,
                               float* __restrict__ out)
{
    const int row = blockIdx.x;
    const float4* xr = (const float4*)(x + (size_t)row * DM);
    const float4* gr = (const float4*)g;
    float4 v = xr[threadIdx.x];
    float s = v.x*v.x + v.y*v.y + v.z*v.z + v.w*v.w;
    #pragma unroll
    for (int o = 16; o > 0; o >>= 1) s += __shfl_xor_sync(0xFFFFFFFFu, s, o);
    __shared__ float red[8];
    if ((threadIdx.x & 31) == 0) red[threadIdx.x >> 5] = s;
    __syncthreads();
    float tot = red[0]+red[1]+red[2]+red[3]+red[4]+red[5]+red[6]+red[7];
    float sc = rsqrtf(tot * (1.0f/(float)DM) + 1e-6f);
    float4 gv = gr[threadIdx.x];
    float4 o4;
    o4.x = v.x * sc * gv.x;
    o4.y = v.y * sc * gv.y;
    o4.z = v.z * sc * gv.z;
    o4.w = v.w * sc * gv.w;
    ((float4*)(out + (size_t)row * DM))[threadIdx.x] = o4;
}

// ---------------- q/k L2-norm per head + LOG-SIGMOID(gate), in place ----------------
__global__ void qknorm_kernel(float* __restrict__ q,
                              float* __restrict__ k,
                              float* __restrict__ a)
{
    const int row  = blockIdx.x;
    const int lane = threadIdx.x & 31;
    const int w    = threadIdx.x >> 5;
    float2* qr = (float2*)(q + (size_t)row * DM);
    float2* kr = (float2*)(k + (size_t)row * DM);

    #pragma unroll
    for (int it = 0; it < 2; ++it) {
        const int h = w + it * 8;
        {
            float2 v = qr[h*32 + lane];
            float s = v.x*v.x + v.y*v.y;
            #pragma unroll
            for (int o = 16; o > 0; o >>= 1) s += __shfl_xor_sync(0xFFFFFFFFu, s, o);
            float inv = 1.0f / fmaxf(sqrtf(s), 1e-12f);
            v.x *= inv; v.y *= inv;
            qr[h*32 + lane] = v;
        }
        {
            float2 v = kr[h*32 + lane];
            float s = v.x*v.x + v.y*v.y;
            #pragma unroll
            for (int o = 16; o > 0; o >>= 1) s += __shfl_xor_sync(0xFFFFFFFFu, s, o);
            float inv = 1.0f / fmaxf(sqrtf(s), 1e-12f);
            v.x *= inv; v.y *= inv;
            kr[h*32 + lane] = v;
        }
    }
    // a <- log(sigmoid(a))  (stable both tails)
    float* ar = a + (size_t)row * DM;
    for (int i = threadIdx.x; i < DM; i += 256) {
        float z = ar[i];
        float l = (z >= 0.0f) ? -log1pf(__expf(-z)) : (z - log1pf(__expf(z)));
        ar[i] = l;
    }
}

// ---------------- Kernel 1: per-chunk cumprods, q~/k~, summary P ----------------
__global__ __launch_bounds__(256) void chunk_summary_kernel(
    float* __restrict__ q, float* __restrict__ k,
    const float* __restrict__ v, const float* __restrict__ la,
    float* __restrict__ P, float* __restrict__ Ae)
{
    __shared__ float Ash[CS][64];
    __shared__ float Ks [CS][64];
    __shared__ float Vs [CS][64];

    const int bhc = blockIdx.x;
    const int bh  = bhc >> 4, c = bhc & 15;
    const int b   = bh >> 4,  h = bh & 15;
    const int tid = threadIdx.x;
    const int d   = tid & 63, j0 = tid >> 6;
    const size_t base = ((size_t)(b*1024 + c*CS)) * DM + h*64;

    #pragma unroll
    for (int i = 0; i < 16; ++i) {
        const int j = j0 + 4*i;
        Ash[j][d] = la[base + (size_t)j*DM + d];
    }
    __syncthreads();

    if (tid < 64) {
        float cum = 0.0f, Aj = 1.0f;
        #pragma unroll
        for (int j = 0; j < CS; ++j) {
            cum += Ash[j][tid];
            Aj = __expf(cum);
            Ash[j][tid] = Aj;
        }
        Ae[(size_t)bhc*64 + tid] = Aj;
    }
    __syncthreads();

    #pragma unroll
    for (int i = 0; i < 16; ++i) {
        const int j = j0 + 4*i;
        const size_t off = base + (size_t)j*DM + d;
        const float A = Ash[j][d];
        q[off] = q[off] * A;
        const float kv = __fdividef(k[off], A);
        k[off] = kv;
        Ks[j][d] = kv;
        Vs[j][d] = v[off];
    }
    __syncthreads();

    const int dr = (tid >> 4) << 2;
    const int ec = (tid & 15) << 2;
    float acc[4][4];
    #pragma unroll
    for (int i = 0; i < 4; ++i)
        #pragma unroll
        for (int j = 0; j < 4; ++j) acc[i][j] = 0.0f;

    #pragma unroll 4
    for (int i2 = 0; i2 < CS; ++i2) {
        float kk[4], vv[4];
        *(float4*)kk = *(const float4*)&Ks[i2][dr];
        *(float4*)vv = *(const float4*)&Vs[i2][ec];
        #pragma unroll
        for (int i = 0; i < 4; ++i)
            #pragma unroll
            for (int j = 0; j < 4; ++j)
                acc[i][j] = fmaf(kk[i], vv[j], acc[i][j]);
    }

    float* Pp = P + (size_t)bhc * 4096;
    #pragma unroll
    for (int ii = 0; ii < 4; ++ii) {
        const float aend = Ash[CS-1][dr+ii];
        float4 o4;
        o4.x = acc[ii][0]*aend; o4.y = acc[ii][1]*aend;
        o4.z = acc[ii][2]*aend; o4.w = acc[ii][3]*aend;
        *(float4*)&Pp[(dr+ii)*64 + ec] = o4;
    }
}

// ---------------- Kernel 2: chunk-level state recurrence (16 steps) ----------------
__global__ __launch_bounds__(256) void chunk_state_kernel(
    const float* __restrict__ P, const float* __restrict__ Ae,
    float* __restrict__ S)
{
    const int bh  = blockIdx.x;
    const int tid = threadIdx.x;
    const int e   = tid & 63;
    const int d0  = tid >> 6;
    __shared__ float sae[64];

    float s[16];
    #pragma unroll
    for (int i = 0; i < 16; ++i) s[i] = 0.0f;

    for (int c = 0; c < NC; ++c) {
        const size_t idx = (size_t)bh*NC + c;
        if (tid < 64) sae[tid] = Ae[idx*64 + tid];
        __syncthreads();
        const float* Pc = P + idx*4096;
        float*       Sc = S + idx*4096;
        #pragma unroll
        for (int i = 0; i < 16; ++i) {
            const int d = d0 + 4*i;
            Sc[d*64 + e] = s[i];
            s[i] = fmaf(sae[d], s[i], Pc[d*64 + e]);
        }
        __syncthreads();
    }
}

// ---------------- Kernel 3: intra-chunk outputs ----------------
__global__ __launch_bounds__(256) void chunk_output_kernel(
    const float* __restrict__ q, const float* __restrict__ k,
    const float* __restrict__ v, const float* __restrict__ S,
    float* __restrict__ o)
{
    extern __shared__ float sm3[];
    float (*Qs)[PAD] = (float(*)[PAD])(sm3);
    float (*KT)[PAD] = (float(*)[PAD])(sm3 + 64*PAD);
    float (*Bs)[PAD] = (float(*)[PAD])(sm3 + 2*64*PAD);
    float (*Sc)[PAD] = (float(*)[PAD])(sm3 + 3*64*PAD);

    const int bhc = blockIdx.x;
    const int bh  = bhc >> 4, c = bhc & 15;
    const int b   = bh >> 4,  h = bh & 15;
    const int tid = threadIdx.x;
    const int d   = tid & 63, j0 = tid >> 6;
    const size_t base = ((size_t)(b*1024 + c*CS)) * DM + h*64;
    const float* Sb = S + (size_t)bhc * 4096;

    #pragma unroll
    for (int i = 0; i < 16; ++i) {
        const int j = j0 + 4*i;
        Qs[j][d] = q[base + (size_t)j*DM + d];
        KT[d][j] = k[base + (size_t)j*DM + d];
        Bs[j][d] = Sb[j*64 + d];
    }
    __syncthreads();

    const int tr = (tid >> 4) << 2;
    const int tc = (tid & 15) << 2;

    float acc[4][4], sca[4][4];
    #pragma unroll
    for (int i = 0; i < 4; ++i)
        #pragma unroll
        for (int j = 0; j < 4; ++j) { acc[i][j] = 0.0f; sca[i][j] = 0.0f; }

    #pragma unroll 4
    for (int dd = 0; dd < 64; ++dd) {
        float bv[4], kv[4], av[4];
        *(float4*)bv = *(const float4*)&Bs[dd][tc];
        *(float4*)kv = *(const float4*)&KT[dd][tc];
        #pragma unroll
        for (int i = 0; i < 4; ++i) av[i] = Qs[tr+i][dd];
        #pragma unroll
        for (int i = 0; i < 4; ++i)
            #pragma unroll
            for (int j = 0; j < 4; ++j) {
                acc[i][j] = fmaf(av[i], bv[j], acc[i][j]);
                sca[i][j] = fmaf(av[i], kv[j], sca[i][j]);
            }
    }

    #pragma unroll
    for (int i = 0; i < 4; ++i)
        #pragma unroll
        for (int j = 0; j < 4; ++j)
            Sc[tr+i][tc+j] = ((tc+j) <= (tr+i)) ? sca[i][j] : 0.0f;
    __syncthreads();

    #pragma unroll
    for (int i = 0; i < 16; ++i) {
        const int j = j0 + 4*i;
        Bs[j][d] = v[base + (size_t)j*DM + d];
    }
    __syncthreads();

    #pragma unroll 4
    for (int dd = 0; dd < 64; ++dd) {
        float bv[4], av[4];
        *(float4*)bv = *(const float4*)&Bs[dd][tc];
        #pragma unroll
        for (int i = 0; i < 4; ++i) av[i] = Sc[tr+i][dd];
        #pragma unroll
        for (int i = 0; i < 4; ++i)
            #pragma unroll
            for (int j = 0; j < 4; ++j)
                acc[i][j] = fmaf(av[i], bv[j], acc[i][j]);
    }

    #pragma unroll
    for (int i = 0; i < 4; ++i) {
        float4 o4;
        o4.x = acc[i][0]; o4.y = acc[i][1]; o4.z = acc[i][2]; o4.w = acc[i][3];
        *(float4*)&o[base + (size_t)(tr+i)*DM + tc] = o4;
    }
}

// ---------------- SGEMM (f32x2 packed FMA): C[z] = A @ B[z] (+R) ----------------
// 64x128 block tile, BK=16, 128 threads, 8x8 per thread via 8x4 float2 accs.
// A duplicated in smem so ld.shared.b64 yields the (a,a) broadcast pair.
struct Ptrs4 {
    const float* B[4];
    float*       C[4];
};

__device__ __forceinline__ void fma_f32x2(u64& acc, u64 a, u64 b)
{
    asm volatile("fma.rn.f32x2 %0, %1, %2, %0;" : "+l"(acc) : "l"(a), "l"(b));
}

template<bool HAS_RES>
__global__ __launch_bounds__(128)
void sgemm_kernel(const float* __restrict__ A, Ptrs4 p,
                  const float* __restrict__ R,
                  int M, int N, int K)
{
    const float* __restrict__ B = p.B[blockIdx.z];
    float* __restrict__       C = p.C[blockIdx.z];

    __shared__ float As[16][136];   // duplicated A pairs: [kk][2m],[kk][2m+1]
    __shared__ float Bs[16][128];

    const int tid = threadIdx.x;
    const int bm = blockIdx.y * 64;
    const int bn = blockIdx.x * 128;
    const int tx = tid & 15;
    const int ty = tid >> 4;

    const int aRow = tid >> 2;           // 0..31
    const int aCol = (tid & 3) * 4;      // 0,4,8,12
    const int bRow = tid >> 5;           // 0..3
    const int bCol = (tid & 31) * 4;     // 0..124
    const bool bOk = (bn + bCol) < N;

    u64 acc[8][4];
    #pragma unroll
    for (int i = 0; i < 8; ++i)
        #pragma unroll
        for (int j = 0; j < 4; ++j) acc[i][j] = 0ULL;

    const float* Ap = A + (size_t)(bm + aRow) * K + aCol;
    const float* Bp = B + (size_t)bRow * N + bn + bCol;

    for (int k0 = 0; k0 < K; k0 += 16) {
        #pragma unroll
        for (int i = 0; i < 2; ++i) {
            float4 va = *(const float4*)(Ap + (size_t)i * 32 * K + k0);
            const int m2 = 2 * (aRow + i * 32);
            *(float2*)&As[aCol+0][m2] = make_float2(va.x, va.x);
            *(float2*)&As[aCol+1][m2] = make_float2(va.y, va.y);
            *(float2*)&As[aCol+2][m2] = make_float2(va.z, va.z);
            *(float2*)&As[aCol+3][m2] = make_float2(va.w, va.w);
        }
        #pragma unroll
        for (int i = 0; i < 4; ++i) {
            float4 vb = make_float4(0.f, 0.f, 0.f, 0.f);
            if (bOk) vb = *(const float4*)(Bp + (size_t)(k0 + i*4) * N);
            *(float4*)&Bs[bRow + i*4][bCol] = vb;
        }
        __syncthreads();

        #pragma unroll
        for (int kk = 0; kk < 16; ++kk) {
            u64 ar[8], br[4];
            #pragma unroll
            for (int i = 0; i < 8; ++i)
                ar[i] = *(const u64*)&As[kk][2*(ty*8 + i)];
            #pragma unroll
            for (int j = 0; j < 4; ++j)
                br[j] = *(const u64*)&Bs[kk][tx*8 + j*2];
            #pragma unroll
            for (int i = 0; i < 8; ++i)
                #pragma unroll
                for (int j = 0; j < 4; ++j)
                    fma_f32x2(acc[i][j], ar[i], br[j]);
        }
        __syncthreads();
    }

    #pragma unroll
    for (int i = 0; i < 8; ++i) {
        const int row = bm + ty*8 + i;
        #pragma unroll
        for (int jj = 0; jj < 2; ++jj) {
            const int col = bn + tx*8 + jj*4;
            if (col < N) {
                float2 p0 = *(float2*)&acc[i][jj*2 + 0];
                float2 p1 = *(float2*)&acc[i][jj*2 + 1];
                float4 o;
                o.x = p0.x; o.y = p0.y; o.z = p1.x; o.w = p1.y;
                if (HAS_RES) {
                    float4 r = *(const float4*)(R + (size_t)row * N + col);
                    o.x += r.x; o.y += r.y; o.z += r.z; o.w += r.w;
                }
                *(float4*)(C + (size_t)row * N + col) = o;
            }
        }
    }
}

// ---------------- SwiGLU: f1 = silu(f1) * f2 ----------------
__global__ void swiglu_kernel(float* __restrict__ f1, const float* __restrict__ f2, int n4)
{
    int i = blockIdx.x * blockDim.x + threadIdx.x;
    if (i < n4) {
        float4 a = ((const float4*)f1)[i];
        float4 b = ((const float4*)f2)[i];
        a.x = a.x / (1.0f + __expf(-a.x)) * b.x;
        a.y = a.y / (1.0f + __expf(-a.y)) * b.y;
        a.z = a.z / (1.0f + __expf(-a.z)) * b.z;
        a.w = a.w / (1.0f + __expf(-a.w)) * b.w;
        ((float4*)f1)[i] = a;
    }
}

// ---------------- host launcher ----------------
extern "C" void kernel_launch(void* const* d_in, const int* in_sizes, int n_in,
                              void* d_out, int out_size)
{
    const float* x     = (const float*)d_in[0];
    const float* Wq    = (const float*)d_in[1];
    const float* Wk    = (const float*)d_in[2];
    const float* Wv    = (const float*)d_in[3];
    const float* Wg    = (const float*)d_in[4];
    const float* Wo    = (const float*)d_in[5];
    const float* w1    = (const float*)d_in[6];
    const float* w2    = (const float*)d_in[7];
    const float* w3    = (const float*)d_in[8];
    const float* gat   = (const float*)d_in[9];
    const float* gff   = (const float*)d_in[10];
    float* out = (float*)d_out;

    float *ph, *pq, *pk, *pv, *pa, *po, *px1, *pf1, *pf2, *pP, *pSs, *pAe;
    cudaGetSymbolAddress((void**)&ph,  g_h);
    cudaGetSymbolAddress((void**)&pq,  g_q);
    cudaGetSymbolAddress((void**)&pk,  g_k);
    cudaGetSymbolAddress((void**)&pv,  g_v);
    cudaGetSymbolAddress((void**)&pa,  g_a);
    cudaGetSymbolAddress((void**)&po,  g_o);
    cudaGetSymbolAddress((void**)&px1, g_x1);
    cudaGetSymbolAddress((void**)&pf1, g_f1);
    cudaGetSymbolAddress((void**)&pf2, g_f2);
    cudaGetSymbolAddress((void**)&pP,  g_P);
    cudaGetSymbolAddress((void**)&pSs, g_Ss);
    cudaGetSymbolAddress((void**)&pAe, g_Ae);

    static bool attr_done = false;
    if (!attr_done) {
        cudaFuncSetAttribute(chunk_output_kernel,
                             cudaFuncAttributeMaxDynamicSharedMemorySize,
                             4 * 64 * PAD * (int)sizeof(float));
        attr_done = true;
    }

    // 1) h = rmsnorm(x, g_attn)
    rmsnorm_kernel<<<BT, 256>>>(x, gat, ph);

    // 2) q,k,v,gate raw = h @ {Wq,Wk,Wv,Wg}
    {
        Ptrs4 p;
        p.B[0] = Wq; p.B[1] = Wk; p.B[2] = Wv; p.B[3] = Wg;
        p.C[0] = pq; p.C[1] = pk; p.C[2] = pv; p.C[3] = pa;
        dim3 grid(DM/128, BT/64, 4);
        sgemm_kernel<false><<<grid, 128>>>(ph, p, nullptr, BT, DM, DM);
    }

    // 3) l2norm(q), l2norm(k), log-sigmoid(gate) in place
    qknorm_kernel<<<BT, 256>>>(pq, pk, pa);

    // 4) chunked GLA
    chunk_summary_kernel<<<NBHC, 256>>>(pq, pk, pv, pa, pP, pAe);
    chunk_state_kernel  <<<32,   256>>>(pP, pAe, pSs);
    chunk_output_kernel <<<NBHC, 256, 4*64*PAD*(int)sizeof(float)>>>(pq, pk, pv, pSs, po);

    // 5) x1 = x + o @ Wo
    {
        Ptrs4 p;
        for (int i = 0; i < 4; ++i) { p.B[i] = Wo; p.C[i] = px1; }
        dim3 grid(DM/128, BT/64, 1);
        sgemm_kernel<true><<<grid, 128>>>(po, p, x, BT, DM, DM);
    }

    // 6) h = rmsnorm(x1, g_ffn)
    rmsnorm_kernel<<<BT, 256>>>(px1, gff, ph);

    // 7) f1 = h @ w1 ; f2 = h @ w2
    {
        Ptrs4 p;
        p.B[0] = w1; p.B[1] = w2; p.B[2] = w1; p.B[3] = w1;
        p.C[0] = pf1; p.C[1] = pf2; p.C[2] = pf1; p.C[3] = pf1;
        dim3 grid((DFF + 127)/128, BT/64, 2);
        sgemm_kernel<false><<<grid, 128>>>(ph, p, nullptr, BT, DFF, DM);
    }

    // 8) f1 = silu(f1) * f2
    {
        int n4 = (BT * DFF) / 4;
        swiglu_kernel<<<(n4 + 255)/256, 256>>>(pf1, pf2, n4);
    }

    // 9) out = x1 + f1 @ w3
    {
        Ptrs4 p;
        for (int i = 0; i < 4; ++i) { p.B[i] = w3; p.C[i] = out; }
        dim3 grid(DM/128, BT/64, 1);
        sgemm_kernel<true><<<grid, 128>>>(pf1, p, px1, BT, DM, DFF);
    }
}

// round 7
// speedup vs baseline: 2.2726x; 2.2726x over previous
#include <cuda_runtime.h>
#include <cuda_bf16.h>
#include <math.h>

#define BT   2048     // B*T
#define DM   1024     // d_model
#define NH   16
#define DKV  64
#define DFF  2736
#define DFFP 2816     // DFF padded to multiple of 128
#define NC   16       // chunks per sequence
#define CS   64       // chunk size
#define NBHC 512      // B*H*NC
#define PAD  68       // smem row stride (floats) for chunk_output

typedef unsigned long long u64;
typedef unsigned int u32;

// ---------------- scratch (static device globals; no allocation) ----------------
__device__ float g_q [BT*DM];
__device__ float g_k [BT*DM];
__device__ float g_v [BT*DM];
__device__ float g_a [BT*DM];
__device__ float g_x1[BT*DM];
__device__ float g_f1[BT*DFFP];
__device__ float g_f2[BT*DFFP];
__device__ float g_P [NBHC*4096];
__device__ float g_Ss[NBHC*4096];
__device__ float g_Ae[NBHC*64];

// bf16 split buffers
__device__ __nv_bfloat16 g_xh [BT*DM];
__device__ __nv_bfloat16 g_xl [BT*DM];
__device__ __nv_bfloat16 g_f1h[BT*DFFP];
__device__ __nv_bfloat16 g_f1l[BT*DFFP];
__device__ __nv_bfloat16 g_WTh [4096*1024];    // QKVG weights transposed [4096][1024]
__device__ __nv_bfloat16 g_WTl [4096*1024];
__device__ __nv_bfloat16 g_WoTh[1024*1024];
__device__ __nv_bfloat16 g_WoTl[1024*1024];
__device__ __nv_bfloat16 g_W12Th[2*DFFP*1024]; // [5632][1024]
__device__ __nv_bfloat16 g_W12Tl[2*DFFP*1024];
__device__ __nv_bfloat16 g_W3Th[1024*DFFP];    // [1024][2816]
__device__ __nv_bfloat16 g_W3Tl[1024*DFFP];

// ---------------- PTX helpers (all sm_80-era, legal on compute_103) ----------------
__device__ __forceinline__ u32 s2u(const void* p) {
    u32 a;
    asm("{ .reg .u64 t; cvta.to.shared.u64 t, %1; cvt.u32.u64 %0, t; }" : "=r"(a) : "l"(p));
    return a;
}
__device__ __forceinline__ void ldsm_x4(u32* r, u32 addr) {
    asm volatile("ldmatrix.sync.aligned.m8n8.x4.shared.b16 {%0,%1,%2,%3}, [%4];"
        : "=r"(r[0]), "=r"(r[1]), "=r"(r[2]), "=r"(r[3]) : "r"(addr));
}
__device__ __forceinline__ void mma16816(float* c, const u32* a, const u32* b) {
    asm volatile(
        "mma.sync.aligned.m16n8k16.row.col.f32.bf16.bf16.f32 "
        "{%0,%1,%2,%3}, {%4,%5,%6,%7}, {%8,%9}, {%0,%1,%2,%3};"
        : "+f"(c[0]), "+f"(c[1]), "+f"(c[2]), "+f"(c[3])
        : "r"(a[0]), "r"(a[1]), "r"(a[2]), "r"(a[3]), "r"(b[0]), "r"(b[1]));
}

// ---------------- bf16-split warp-MMA GEMM ----------------
// C[M,Ntot] = A[M,K] @ W[K,Ntot] (+R); A,W pre-split to bf16 hi/lo,
// W pre-transposed to [Ntot][K] (so mma row.col works directly).
// 128x128 CTA tile, BK=64, 256 threads = 8 warps (2m x 4n), warp tile 64x32.
#define RSB 144                    // smem row stride bytes (128B data + 16B pad)
#define TILE_BYTES (128*RSB)       // 18432
#define GEMM_SMEM (4*TILE_BYTES)   // 73728

__global__ __launch_bounds__(256) void bfgemm_kernel(
    const __nv_bfloat16* __restrict__ Ah, const __nv_bfloat16* __restrict__ Al,
    const __nv_bfloat16* __restrict__ Bh, const __nv_bfloat16* __restrict__ Bl,
    float* C0, float* C1, float* C2, float* C3,
    const float* __restrict__ R,
    int K, int Nper)
{
    extern __shared__ char sm[];
    char* sAh = sm;
    char* sAl = sm + TILE_BYTES;
    char* sBh = sm + 2*TILE_BYTES;
    char* sBl = sm + 3*TILE_BYTES;
    const u32 uAh = s2u(sAh), uAl = s2u(sAl), uBh = s2u(sBh), uBl = s2u(sBl);

    const int tid  = threadIdx.x;
    const int lane = tid & 31;
    const int wid  = tid >> 5;
    const int wr   = wid >> 2;     // 0..1  (m)
    const int wc   = wid & 3;      // 0..3  (n)
    const int bn = blockIdx.x * 128;
    const int bm = blockIdx.y * 128;

    const int lrow  = tid >> 1;    // 0..127
    const int lhalf = tid & 1;     // which 64B half of the 128B row

    float acc[4][4][4];
    #pragma unroll
    for (int i = 0; i < 4; ++i)
        #pragma unroll
        for (int j = 0; j < 4; ++j)
            #pragma unroll
            for (int q = 0; q < 4; ++q) acc[i][j][q] = 0.0f;

    const char* gAh = (const char*)(Ah + (size_t)(bm + lrow) * K) + lhalf * 64;
    const char* gAl = (const char*)(Al + (size_t)(bm + lrow) * K) + lhalf * 64;
    const char* gBh = (const char*)(Bh + (size_t)(bn + lrow) * K) + lhalf * 64;
    const char* gBl = (const char*)(Bl + (size_t)(bn + lrow) * K) + lhalf * 64;
    const u32 so = (u32)lrow * RSB + (u32)lhalf * 64;

    for (int k0 = 0; k0 < K; k0 += 64) {
        const int kb = k0 * 2;     // byte offset into bf16 row
        #pragma unroll
        for (int i = 0; i < 4; ++i) {
            *(uint4*)(sAh + so + i*16) = *(const uint4*)(gAh + kb + i*16);
            *(uint4*)(sAl + so + i*16) = *(const uint4*)(gAl + kb + i*16);
            *(uint4*)(sBh + so + i*16) = *(const uint4*)(gBh + kb + i*16);
            *(uint4*)(sBl + so + i*16) = *(const uint4*)(gBl + kb + i*16);
        }
        __syncthreads();

        #pragma unroll
        for (int ks = 0; ks < 4; ++ks) {
            const u32 coff = (u32)ks * 32 + ((u32)(lane >> 4)) * 16;
            const u32 rsel = (u32)(lane & 15);
            u32 ah[4][4], al[4][4], bh[4][2], bl[4][2];

            #pragma unroll
            for (int mi = 0; mi < 4; ++mi) {
                const u32 ra = (u32)(wr*64 + mi*16) * RSB + rsel * RSB + coff;
                ldsm_x4(ah[mi], uAh + ra);
                ldsm_x4(al[mi], uAl + ra);
            }
            #pragma unroll
            for (int jj = 0; jj < 2; ++jj) {
                const u32 rb = (u32)(wc*32 + jj*16) * RSB + rsel * RSB + coff;
                u32 t[4];
                ldsm_x4(t, uBh + rb);
                bh[jj*2+0][0] = t[0]; bh[jj*2+0][1] = t[2];
                bh[jj*2+1][0] = t[1]; bh[jj*2+1][1] = t[3];
                ldsm_x4(t, uBl + rb);
                bl[jj*2+0][0] = t[0]; bl[jj*2+0][1] = t[2];
                bl[jj*2+1][0] = t[1]; bl[jj*2+1][1] = t[3];
            }

            #pragma unroll
            for (int mi = 0; mi < 4; ++mi)
                #pragma unroll
                for (int nj = 0; nj < 4; ++nj) {
                    mma16816(acc[mi][nj], ah[mi], bh[nj]);
                    mma16816(acc[mi][nj], ah[mi], bl[nj]);
                    mma16816(acc[mi][nj], al[mi], bh[nj]);
                }
        }
        __syncthreads();
    }

    // epilogue: fragment c0,c1 -> row g; c2,c3 -> row g+8; cols 2t,2t+1
    const int arr = bn / Nper;
    float* C = (arr == 0) ? C0 : (arr == 1) ? C1 : (arr == 2) ? C2 : C3;
    const int cb = bn - arr * Nper;

    #pragma unroll
    for (int mi = 0; mi < 4; ++mi) {
        const int r0 = bm + wr*64 + mi*16 + (lane >> 2);
        #pragma unroll
        for (int nj = 0; nj < 4; ++nj) {
            const int col = cb + wc*32 + nj*8 + (lane & 3)*2;
            float2 v0 = make_float2(acc[mi][nj][0], acc[mi][nj][1]);
            float2 v1 = make_float2(acc[mi][nj][2], acc[mi][nj][3]);
            if (R) {
                const float2 q0 = *(const float2*)(R + (size_t)r0 * Nper + col);
                const float2 q1 = *(const float2*)(R + (size_t)(r0+8) * Nper + col);
                v0.x += q0.x; v0.y += q0.y;
                v1.x += q1.x; v1.y += q1.y;
            }
            *(float2*)(C + (size_t)r0     * Nper + col) = v0;
            *(float2*)(C + (size_t)(r0+8) * Nper + col) = v1;
        }
    }
}

// ---------------- transpose + bf16 split: W[K,N] -> WT_hi/lo[N(+off)][Kdst] ----------
__global__ void transpose_split_kernel(const float* __restrict__ src,
                                       __nv_bfloat16* __restrict__ dh,
                                       __nv_bfloat16* __restrict__ dl,
                                       int K, int N, int Kdst, int rowOff)
{
    __shared__ float t[32][33];
    const int k0 = blockIdx.x * 32;
    const int n0 = blockIdx.y * 32;
    const int tx = threadIdx.x, ty = threadIdx.y;

    #pragma unroll
    for (int i = 0; i < 4; ++i) {
        const int kk = k0 + ty + i*8;
        const int nn = n0 + tx;
        t[ty + i*8][tx] = (kk < K && nn < N) ? src[(size_t)kk * N + nn] : 0.0f;
    }
    __syncthreads();
    #pragma unroll
    for (int i = 0; i < 4; ++i) {
        const int nn = n0 + ty + i*8;
        const int kk = k0 + tx;
        const float v = t[tx][ty + i*8];
        const __nv_bfloat16 h = __float2bfloat16(v);
        const float res = v - __bfloat162float(h);
        const size_t di = (size_t)(nn + rowOff) * Kdst + kk;
        dh[di] = h;
        dl[di] = __float2bfloat16(res);
    }
}

// ---------------- RMSNorm fused with bf16 split ----------------
__global__ void rmsnorm_split_kernel(const float* __restrict__ x,
                                     const float* __restrict__ g,
                                     __nv_bfloat16* __restrict__ oh,
                                     __nv_bfloat16* __restrict__ ol)
{
    const int row = blockIdx.x;
    const float4* xr = (const float4*)(x + (size_t)row * DM);
    const float4* gr = (const float4*)g;
    float4 v = xr[threadIdx.x];
    float s = v.x*v.x + v.y*v.y + v.z*v.z + v.w*v.w;
    #pragma unroll
    for (int o = 16; o > 0; o >>= 1) s += __shfl_xor_sync(0xFFFFFFFFu, s, o);
    __shared__ float red[8];
    if ((threadIdx.x & 31) == 0) red[threadIdx.x >> 5] = s;
    __syncthreads();
    float tot = red[0]+red[1]+red[2]+red[3]+red[4]+red[5]+red[6]+red[7];
    float sc = rsqrtf(tot * (1.0f/(float)DM) + 1e-6f);
    float4 gv = gr[threadIdx.x];
    float hv[4];
    hv[0] = v.x * sc * gv.x;
    hv[1] = v.y * sc * gv.y;
    hv[2] = v.z * sc * gv.z;
    hv[3] = v.w * sc * gv.w;
    const size_t base = (size_t)row * DM + threadIdx.x * 4;
    #pragma unroll
    for (int j = 0; j < 4; ++j) {
        const __nv_bfloat16 h = __float2bfloat16(hv[j]);
        oh[base + j] = h;
        ol[base + j] = __float2bfloat16(hv[j] - __bfloat162float(h));
    }
}

// ---------------- q/k L2-norm per head + LOG-SIGMOID(gate), in place ----------------
__global__ void qknorm_kernel(float* __restrict__ q,
                              float* __restrict__ k,
                              float* __restrict__ a)
{
    const int row  = blockIdx.x;
    const int lane = threadIdx.x & 31;
    const int w    = threadIdx.x >> 5;
    float2* qr = (float2*)(q + (size_t)row * DM);
    float2* kr = (float2*)(k + (size_t)row * DM);

    #pragma unroll
    for (int it = 0; it < 2; ++it) {
        const int h = w + it * 8;
        {
            float2 v = qr[h*32 + lane];
            float s = v.x*v.x + v.y*v.y;
            #pragma unroll
            for (int o = 16; o > 0; o >>= 1) s += __shfl_xor_sync(0xFFFFFFFFu, s, o);
            float inv = 1.0f / fmaxf(sqrtf(s), 1e-12f);
            v.x *= inv; v.y *= inv;
            qr[h*32 + lane] = v;
        }
        {
            float2 v = kr[h*32 + lane];
            float s = v.x*v.x + v.y*v.y;
            #pragma unroll
            for (int o = 16; o > 0; o >>= 1) s += __shfl_xor_sync(0xFFFFFFFFu, s, o);
            float inv = 1.0f / fmaxf(sqrtf(s), 1e-12f);
            v.x *= inv; v.y *= inv;
            kr[h*32 + lane] = v;
        }
    }
    float* ar = a + (size_t)row * DM;
    for (int i = threadIdx.x; i < DM; i += 256) {
        float z = ar[i];
        ar[i] = (z >= 0.0f) ? -log1pf(__expf(-z)) : (z - log1pf(__expf(z)));
    }
}

// ---------------- chunked GLA kernels ----------------
__global__ __launch_bounds__(256) void chunk_summary_kernel(
    float* __restrict__ q, float* __restrict__ k,
    const float* __restrict__ v, const float* __restrict__ la,
    float* __restrict__ P, float* __restrict__ Ae)
{
    __shared__ float Ash[CS][64];
    __shared__ float Ks [CS][64];
    __shared__ float Vs [CS][64];

    const int bhc = blockIdx.x;
    const int bh  = bhc >> 4, c = bhc & 15;
    const int b   = bh >> 4,  h = bh & 15;
    const int tid = threadIdx.x;
    const int d   = tid & 63, j0 = tid >> 6;
    const size_t base = ((size_t)(b*1024 + c*CS)) * DM + h*64;

    #pragma unroll
    for (int i = 0; i < 16; ++i) {
        const int j = j0 + 4*i;
        Ash[j][d] = la[base + (size_t)j*DM + d];
    }
    __syncthreads();

    if (tid < 64) {
        float cum = 0.0f, Aj = 1.0f;
        #pragma unroll
        for (int j = 0; j < CS; ++j) {
            cum += Ash[j][tid];
            Aj = __expf(cum);
            Ash[j][tid] = Aj;
        }
        Ae[(size_t)bhc*64 + tid] = Aj;
    }
    __syncthreads();

    #pragma unroll
    for (int i = 0; i < 16; ++i) {
        const int j = j0 + 4*i;
        const size_t off = base + (size_t)j*DM + d;
        const float A = Ash[j][d];
        q[off] = q[off] * A;
        const float kv = __fdividef(k[off], A);
        k[off] = kv;
        Ks[j][d] = kv;
        Vs[j][d] = v[off];
    }
    __syncthreads();

    const int dr = (tid >> 4) << 2;
    const int ec = (tid & 15) << 2;
    float acc[4][4];
    #pragma unroll
    for (int i = 0; i < 4; ++i)
        #pragma unroll
        for (int j = 0; j < 4; ++j) acc[i][j] = 0.0f;

    #pragma unroll 4
    for (int i2 = 0; i2 < CS; ++i2) {
        float kk[4], vv[4];
        *(float4*)kk = *(const float4*)&Ks[i2][dr];
        *(float4*)vv = *(const float4*)&Vs[i2][ec];
        #pragma unroll
        for (int i = 0; i < 4; ++i)
            #pragma unroll
            for (int j = 0; j < 4; ++j)
                acc[i][j] = fmaf(kk[i], vv[j], acc[i][j]);
    }

    float* Pp = P + (size_t)bhc * 4096;
    #pragma unroll
    for (int ii = 0; ii < 4; ++ii) {
        const float aend = Ash[CS-1][dr+ii];
        float4 o4;
        o4.x = acc[ii][0]*aend; o4.y = acc[ii][1]*aend;
        o4.z = acc[ii][2]*aend; o4.w = acc[ii][3]*aend;
        *(float4*)&Pp[(dr+ii)*64 + ec] = o4;
    }
}

__global__ __launch_bounds__(256) void chunk_state_kernel(
    const float* __restrict__ P, const float* __restrict__ Ae,
    float* __restrict__ S)
{
    const int bh  = blockIdx.x;
    const int tid = threadIdx.x;
    const int e   = tid & 63;
    const int d0  = tid >> 6;
    __shared__ float sae[64];

    float s[16];
    #pragma unroll
    for (int i = 0; i < 16; ++i) s[i] = 0.0f;

    for (int c = 0; c < NC; ++c) {
        const size_t idx = (size_t)bh*NC + c;
        if (tid < 64) sae[tid] = Ae[idx*64 + tid];
        __syncthreads();
        const float* Pc = P + idx*4096;
        float*       Sc = S + idx*4096;
        #pragma unroll
        for (int i = 0; i < 16; ++i) {
            const int d = d0 + 4*i;
            Sc[d*64 + e] = s[i];
            s[i] = fmaf(sae[d], s[i], Pc[d*64 + e]);
        }
        __syncthreads();
    }
}

__global__ __launch_bounds__(256) void chunk_output_kernel(
    const float* __restrict__ q, const float* __restrict__ k,
    const float* __restrict__ v, const float* __restrict__ S,
    __nv_bfloat16* __restrict__ oh, __nv_bfloat16* __restrict__ ol)
{
    extern __shared__ float sm3[];
    float (*Qs)[PAD] = (float(*)[PAD])(sm3);
    float (*KT)[PAD] = (float(*)[PAD])(sm3 + 64*PAD);
    float (*Bs)[PAD] = (float(*)[PAD])(sm3 + 2*64*PAD);
    float (*Sc)[PAD] = (float(*)[PAD])(sm3 + 3*64*PAD);

    const int bhc = blockIdx.x;
    const int bh  = bhc >> 4, c = bhc & 15;
    const int b   = bh >> 4,  h = bh & 15;
    const int tid = threadIdx.x;
    const int d   = tid & 63, j0 = tid >> 6;
    const size_t base = ((size_t)(b*1024 + c*CS)) * DM + h*64;
    const float* Sb = S + (size_t)bhc * 4096;

    #pragma unroll
    for (int i = 0; i < 16; ++i) {
        const int j = j0 + 4*i;
        Qs[j][d] = q[base + (size_t)j*DM + d];
        KT[d][j] = k[base + (size_t)j*DM + d];
        Bs[j][d] = Sb[j*64 + d];
    }
    __syncthreads();

    const int tr = (tid >> 4) << 2;
    const int tc = (tid & 15) << 2;

    float acc[4][4], sca[4][4];
    #pragma unroll
    for (int i = 0; i < 4; ++i)
        #pragma unroll
        for (int j = 0; j < 4; ++j) { acc[i][j] = 0.0f; sca[i][j] = 0.0f; }

    #pragma unroll 4
    for (int dd = 0; dd < 64; ++dd) {
        float bv[4], kv[4], av[4];
        *(float4*)bv = *(const float4*)&Bs[dd][tc];
        *(float4*)kv = *(const float4*)&KT[dd][tc];
        #pragma unroll
        for (int i = 0; i < 4; ++i) av[i] = Qs[tr+i][dd];
        #pragma unroll
        for (int i = 0; i < 4; ++i)
            #pragma unroll
            for (int j = 0; j < 4; ++j) {
                acc[i][j] = fmaf(av[i], bv[j], acc[i][j]);
                sca[i][j] = fmaf(av[i], kv[j], sca[i][j]);
            }
    }

    #pragma unroll
    for (int i = 0; i < 4; ++i)
        #pragma unroll
        for (int j = 0; j < 4; ++j)
            Sc[tr+i][tc+j] = ((tc+j) <= (tr+i)) ? sca[i][j] : 0.0f;
    __syncthreads();

    #pragma unroll
    for (int i = 0; i < 16; ++i) {
        const int j = j0 + 4*i;
        Bs[j][d] = v[base + (size_t)j*DM + d];
    }
    __syncthreads();

    #pragma unroll 4
    for (int dd = 0; dd < 64; ++dd) {
        float bv[4], av[4];
        *(float4*)bv = *(const float4*)&Bs[dd][tc];
        #pragma unroll
        for (int i = 0; i < 4; ++i) av[i] = Sc[tr+i][dd];
        #pragma unroll
        for (int i = 0; i < 4; ++i)
            #pragma unroll
            for (int j = 0; j < 4; ++j)
                acc[i][j] = fmaf(av[i], bv[j], acc[i][j]);
    }

    #pragma unroll
    for (int i = 0; i < 4; ++i) {
        const size_t off = base + (size_t)(tr+i)*DM + tc;
        #pragma unroll
        for (int j = 0; j < 4; ++j) {
            const float vvo = acc[i][j];
            const __nv_bfloat16 hh = __float2bfloat16(vvo);
            oh[off + j] = hh;
            ol[off + j] = __float2bfloat16(vvo - __bfloat162float(hh));
        }
    }
}

// ---------------- SwiGLU fused with bf16 split ----------------
__global__ void swiglu_split_kernel(const float* __restrict__ f1,
                                    const float* __restrict__ f2,
                                    __nv_bfloat16* __restrict__ gh,
                                    __nv_bfloat16* __restrict__ gl,
                                    int n4)
{
    int i = blockIdx.x * blockDim.x + threadIdx.x;
    if (i < n4) {
        float4 a = ((const float4*)f1)[i];
        float4 b = ((const float4*)f2)[i];
        float r[4];
        r[0] = a.x / (1.0f + __expf(-a.x)) * b.x;
        r[1] = a.y / (1.0f + __expf(-a.y)) * b.y;
        r[2] = a.z / (1.0f + __expf(-a.z)) * b.z;
        r[3] = a.w / (1.0f + __expf(-a.w)) * b.w;
        #pragma unroll
        for (int j = 0; j < 4; ++j) {
            const __nv_bfloat16 h = __float2bfloat16(r[j]);
            gh[i*4 + j] = h;
            gl[i*4 + j] = __float2bfloat16(r[j] - __bfloat162float(h));
        }
    }
}

// ---------------- host launcher ----------------
extern "C" void kernel_launch(void* const* d_in, const int* in_sizes, int n_in,
                              void* d_out, int out_size)
{
    const float* x   = (const float*)d_in[0];
    const float* Wq  = (const float*)d_in[1];
    const float* Wk  = (const float*)d_in[2];
    const float* Wv  = (const float*)d_in[3];
    const float* Wg  = (const float*)d_in[4];
    const float* Wo  = (const float*)d_in[5];
    const float* w1  = (const float*)d_in[6];
    const float* w2  = (const float*)d_in[7];
    const float* w3  = (const float*)d_in[8];
    const float* gat = (const float*)d_in[9];
    const float* gff = (const float*)d_in[10];
    float* out = (float*)d_out;

    float *pq, *pk, *pv, *pa, *px1, *pf1, *pf2, *pP, *pSs, *pAe;
    __nv_bfloat16 *pxh, *pxl, *pf1h, *pf1l;
    __nv_bfloat16 *pWTh, *pWTl, *pWoTh, *pWoTl, *pW12Th, *pW12Tl, *pW3Th, *pW3Tl;
    cudaGetSymbolAddress((void**)&pq,  g_q);
    cudaGetSymbolAddress((void**)&pk,  g_k);
    cudaGetSymbolAddress((void**)&pv,  g_v);
    cudaGetSymbolAddress((void**)&pa,  g_a);
    cudaGetSymbolAddress((void**)&px1, g_x1);
    cudaGetSymbolAddress((void**)&pf1, g_f1);
    cudaGetSymbolAddress((void**)&pf2, g_f2);
    cudaGetSymbolAddress((void**)&pP,  g_P);
    cudaGetSymbolAddress((void**)&pSs, g_Ss);
    cudaGetSymbolAddress((void**)&pAe, g_Ae);
    cudaGetSymbolAddress((void**)&pxh, g_xh);
    cudaGetSymbolAddress((void**)&pxl, g_xl);
    cudaGetSymbolAddress((void**)&pf1h, g_f1h);
    cudaGetSymbolAddress((void**)&pf1l, g_f1l);
    cudaGetSymbolAddress((void**)&pWTh, g_WTh);
    cudaGetSymbolAddress((void**)&pWTl, g_WTl);
    cudaGetSymbolAddress((void**)&pWoTh, g_WoTh);
    cudaGetSymbolAddress((void**)&pWoTl, g_WoTl);
    cudaGetSymbolAddress((void**)&pW12Th, g_W12Th);
    cudaGetSymbolAddress((void**)&pW12Tl, g_W12Tl);
    cudaGetSymbolAddress((void**)&pW3Th, g_W3Th);
    cudaGetSymbolAddress((void**)&pW3Tl, g_W3Tl);

    static bool attr_done = false;
    if (!attr_done) {
        cudaFuncSetAttribute(chunk_output_kernel,
                             cudaFuncAttributeMaxDynamicSharedMemorySize,
                             4 * 64 * PAD * (int)sizeof(float));
        cudaFuncSetAttribute(bfgemm_kernel,
                             cudaFuncAttributeMaxDynamicSharedMemorySize,
                             GEMM_SMEM);
        attr_done = true;
    }

    dim3 tb(32, 8);
    // 0) transpose + split all weights
    transpose_split_kernel<<<dim3(32, 32), tb>>>(Wq, pWTh, pWTl, 1024, 1024, 1024, 0);
    transpose_split_kernel<<<dim3(32, 32), tb>>>(Wk, pWTh, pWTl, 1024, 1024, 1024, 1024);
    transpose_split_kernel<<<dim3(32, 32), tb>>>(Wv, pWTh, pWTl, 1024, 1024, 1024, 2048);
    transpose_split_kernel<<<dim3(32, 32), tb>>>(Wg, pWTh, pWTl, 1024, 1024, 1024, 3072);
    transpose_split_kernel<<<dim3(32, 32), tb>>>(Wo, pWoTh, pWoTl, 1024, 1024, 1024, 0);
    transpose_split_kernel<<<dim3(32, DFFP/32), tb>>>(w1, pW12Th, pW12Tl, 1024, DFF, 1024, 0);
    transpose_split_kernel<<<dim3(32, DFFP/32), tb>>>(w2, pW12Th, pW12Tl, 1024, DFF, 1024, DFFP);
    transpose_split_kernel<<<dim3(DFFP/32, 32), tb>>>(w3, pW3Th, pW3Tl, DFF, 1024, DFFP, 0);

    // 1) h = rmsnorm(x, g_attn), split to bf16 hi/lo
    rmsnorm_split_kernel<<<BT, 256>>>(x, gat, pxh, pxl);

    // 2) q,k,v,gate = h @ {Wq,Wk,Wv,Wg}  (one N=4096 GEMM)
    bfgemm_kernel<<<dim3(4096/128, BT/128), 256, GEMM_SMEM>>>(
        pxh, pxl, pWTh, pWTl, pq, pk, pv, pa, nullptr, 1024, 1024);

    // 3) l2norm(q), l2norm(k), log-sigmoid(gate)
    qknorm_kernel<<<BT, 256>>>(pq, pk, pa);

    // 4) chunked GLA -> o (split bf16)
    chunk_summary_kernel<<<NBHC, 256>>>(pq, pk, pv, pa, pP, pAe);
    chunk_state_kernel  <<<32,   256>>>(pP, pAe, pSs);
    chunk_output_kernel <<<NBHC, 256, 4*64*PAD*(int)sizeof(float)>>>(pq, pk, pv, pSs, pxh, pxl);

    // 5) x1 = x + o @ Wo
    bfgemm_kernel<<<dim3(1024/128, BT/128), 256, GEMM_SMEM>>>(
        pxh, pxl, pWoTh, pWoTl, px1, nullptr, nullptr, nullptr, x, 1024, 1024);

    // 6) h = rmsnorm(x1, g_ffn), split
    rmsnorm_split_kernel<<<BT, 256>>>(px1, gff, pxh, pxl);

    // 7) f1 = h @ w1 ; f2 = h @ w2   (one N=5632 GEMM, padded)
    bfgemm_kernel<<<dim3(2*DFFP/128, BT/128), 256, GEMM_SMEM>>>(
        pxh, pxl, pW12Th, pW12Tl, pf1, pf2, nullptr, nullptr, nullptr, 1024, DFFP);

    // 8) gated = silu(f1) * f2, split to bf16
    {
        const int n4 = BT * DFFP / 4;
        swiglu_split_kernel<<<(n4 + 255)/256, 256>>>(pf1, pf2, pf1h, pf1l, n4);
    }

    // 9) out = x1 + gated @ w3  (K = 2816 padded)
    bfgemm_kernel<<<dim3(1024/128, BT/128), 256, GEMM_SMEM>>>(
        pf1h, pf1l, pW3Th, pW3Tl, out, nullptr, nullptr, nullptr, px1, DFFP, 1024);
}

// round 8
// speedup vs baseline: 2.2747x; 1.0010x over previous
#include <cuda_runtime.h>
#include <cuda_bf16.h>
#include <math.h>

#define BT   2048     // B*T
#define DM   1024     // d_model
#define NH   16
#define DKV  64
#define DFF  2736
#define DFFP 2816     // DFF padded to multiple of 128
#define NC   16       // chunks per sequence
#define CS   64       // chunk size
#define NBHC 512      // B*H*NC
#define PAD  68       // smem row stride (floats) for chunk_output

typedef unsigned long long u64;
typedef unsigned int u32;

// ---------------- scratch (static device globals; no allocation) ----------------
__device__ float g_q [BT*DM];
__device__ float g_k [BT*DM];
__device__ float g_v [BT*DM];
__device__ float g_a [BT*DM];
__device__ float g_x1[BT*DM];
__device__ float g_f1[BT*DFFP];
__device__ float g_f2[BT*DFFP];
__device__ float g_P [NBHC*4096];
__device__ float g_Ss[NBHC*4096];
__device__ float g_Ae[NBHC*64];

// bf16 split buffers
__device__ __nv_bfloat16 g_xh [BT*DM];
__device__ __nv_bfloat16 g_xl [BT*DM];
__device__ __nv_bfloat16 g_f1h[BT*DFFP];
__device__ __nv_bfloat16 g_f1l[BT*DFFP];
__device__ __nv_bfloat16 g_WTh [4096*1024];    // QKVG weights transposed [4096][1024]
__device__ __nv_bfloat16 g_WTl [4096*1024];
__device__ __nv_bfloat16 g_WoTh[1024*1024];
__device__ __nv_bfloat16 g_WoTl[1024*1024];
__device__ __nv_bfloat16 g_W12Th[2*DFFP*1024]; // [5632][1024]
__device__ __nv_bfloat16 g_W12Tl[2*DFFP*1024];
__device__ __nv_bfloat16 g_W3Th[1024*DFFP];    // [1024][2816]
__device__ __nv_bfloat16 g_W3Tl[1024*DFFP];

// ---------------- PTX helpers (all sm_80-era, legal on compute_103) ----------------
__device__ __forceinline__ u32 s2u(const void* p) {
    u32 a;
    asm("{ .reg .u64 t; cvta.to.shared.u64 t, %1; cvt.u32.u64 %0, t; }" : "=r"(a) : "l"(p));
    return a;
}
__device__ __forceinline__ void ldsm_x4(u32* r, u32 addr) {
    asm volatile("ldmatrix.sync.aligned.m8n8.x4.shared.b16 {%0,%1,%2,%3}, [%4];"
        : "=r"(r[0]), "=r"(r[1]), "=r"(r[2]), "=r"(r[3]) : "r"(addr));
}
__device__ __forceinline__ void mma16816(float* c, const u32* a, const u32* b) {
    asm volatile(
        "mma.sync.aligned.m16n8k16.row.col.f32.bf16.bf16.f32 "
        "{%0,%1,%2,%3}, {%4,%5,%6,%7}, {%8,%9}, {%0,%1,%2,%3};"
        : "+f"(c[0]), "+f"(c[1]), "+f"(c[2]), "+f"(c[3])
        : "r"(a[0]), "r"(a[1]), "r"(a[2]), "r"(a[3]), "r"(b[0]), "r"(b[1]));
}

// ---------------- bf16-split warp-MMA GEMM ----------------
// C[M,Ntot] = A[M,K] @ W[K,Ntot] (+R); A,W pre-split to bf16 hi/lo,
// W pre-transposed to [Ntot][K] (so mma row.col works directly).
// 128x128 CTA tile, BK=64, 256 threads = 8 warps (2m x 4n), warp tile 64x32.
#define RSB 144                    // smem row stride bytes (128B data + 16B pad)
#define TILE_BYTES (128*RSB)       // 18432
#define GEMM_SMEM (4*TILE_BYTES)   // 73728

__global__ __launch_bounds__(256) void bfgemm_kernel(
    const __nv_bfloat16* __restrict__ Ah, const __nv_bfloat16* __restrict__ Al,
    const __nv_bfloat16* __restrict__ Bh, const __nv_bfloat16* __restrict__ Bl,
    float* C0, float* C1, float* C2, float* C3,
    const float* __restrict__ R,
    int K, int Nper)
{
    extern __shared__ char sm[];
    char* sAh = sm;
    char* sAl = sm + TILE_BYTES;
    char* sBh = sm + 2*TILE_BYTES;
    char* sBl = sm + 3*TILE_BYTES;
    const u32 uAh = s2u(sAh), uAl = s2u(sAl), uBh = s2u(sBh), uBl = s2u(sBl);

    const int tid  = threadIdx.x;
    const int lane = tid & 31;
    const int wid  = tid >> 5;
    const int wr   = wid >> 2;     // 0..1  (m)
    const int wc   = wid & 3;      // 0..3  (n)
    const int bn = blockIdx.x * 128;
    const int bm = blockIdx.y * 128;

    const int lrow  = tid >> 1;    // 0..127
    const int lhalf = tid & 1;     // which 64B half of the 128B row

    float acc[4][4][4];
    #pragma unroll
    for (int i = 0; i < 4; ++i)
        #pragma unroll
        for (int j = 0; j < 4; ++j)
            #pragma unroll
            for (int q = 0; q < 4; ++q) acc[i][j][q] = 0.0f;

    const char* gAh = (const char*)(Ah + (size_t)(bm + lrow) * K) + lhalf * 64;
    const char* gAl = (const char*)(Al + (size_t)(bm + lrow) * K) + lhalf * 64;
    const char* gBh = (const char*)(Bh + (size_t)(bn + lrow) * K) + lhalf * 64;
    const char* gBl = (const char*)(Bl + (size_t)(bn + lrow) * K) + lhalf * 64;
    const u32 so = (u32)lrow * RSB + (u32)lhalf * 64;

    for (int k0 = 0; k0 < K; k0 += 64) {
        const int kb = k0 * 2;     // byte offset into bf16 row
        #pragma unroll
        for (int i = 0; i < 4; ++i) {
            *(uint4*)(sAh + so + i*16) = *(const uint4*)(gAh + kb + i*16);
            *(uint4*)(sAl + so + i*16) = *(const uint4*)(gAl + kb + i*16);
            *(uint4*)(sBh + so + i*16) = *(const uint4*)(gBh + kb + i*16);
            *(uint4*)(sBl + so + i*16) = *(const uint4*)(gBl + kb + i*16);
        }
        __syncthreads();

        #pragma unroll
        for (int ks = 0; ks < 4; ++ks) {
            const u32 coff = (u32)ks * 32 + ((u32)(lane >> 4)) * 16;
            const u32 rsel = (u32)(lane & 15);
            u32 ah[4][4], al[4][4], bh[4][2], bl[4][2];

            #pragma unroll
            for (int mi = 0; mi < 4; ++mi) {
                const u32 ra = (u32)(wr*64 + mi*16) * RSB + rsel * RSB + coff;
                ldsm_x4(ah[mi], uAh + ra);
                ldsm_x4(al[mi], uAl + ra);
            }
            #pragma unroll
            for (int jj = 0; jj < 2; ++jj) {
                const u32 rb = (u32)(wc*32 + jj*16) * RSB + rsel * RSB + coff;
                u32 t[4];
                ldsm_x4(t, uBh + rb);
                bh[jj*2+0][0] = t[0]; bh[jj*2+0][1] = t[2];
                bh[jj*2+1][0] = t[1]; bh[jj*2+1][1] = t[3];
                ldsm_x4(t, uBl + rb);
                bl[jj*2+0][0] = t[0]; bl[jj*2+0][1] = t[2];
                bl[jj*2+1][0] = t[1]; bl[jj*2+1][1] = t[3];
            }

            #pragma unroll
            for (int mi = 0; mi < 4; ++mi)
                #pragma unroll
                for (int nj = 0; nj < 4; ++nj) {
                    mma16816(acc[mi][nj], ah[mi], bh[nj]);
                    mma16816(acc[mi][nj], ah[mi], bl[nj]);
                    mma16816(acc[mi][nj], al[mi], bh[nj]);
                }
        }
        __syncthreads();
    }

    // epilogue: fragment c0,c1 -> row g; c2,c3 -> row g+8; cols 2t,2t+1
    const int arr = bn / Nper;
    float* C = (arr == 0) ? C0 : (arr == 1) ? C1 : (arr == 2) ? C2 : C3;
    const int cb = bn - arr * Nper;

    #pragma unroll
    for (int mi = 0; mi < 4; ++mi) {
        const int r0 = bm + wr*64 + mi*16 + (lane >> 2);
        #pragma unroll
        for (int nj = 0; nj < 4; ++nj) {
            const int col = cb + wc*32 + nj*8 + (lane & 3)*2;
            float2 v0 = make_float2(acc[mi][nj][0], acc[mi][nj][1]);
            float2 v1 = make_float2(acc[mi][nj][2], acc[mi][nj][3]);
            if (R) {
                const float2 q0 = *(const float2*)(R + (size_t)r0 * Nper + col);
                const float2 q1 = *(const float2*)(R + (size_t)(r0+8) * Nper + col);
                v0.x += q0.x; v0.y += q0.y;
                v1.x += q1.x; v1.y += q1.y;
            }
            *(float2*)(C + (size_t)r0     * Nper + col) = v0;
            *(float2*)(C + (size_t)(r0+8) * Nper + col) = v1;
        }
    }
}

// ---------------- transpose + bf16 split: W[K,N] -> WT_hi/lo[N(+off)][Kdst] ----------
__global__ void transpose_split_kernel(const float* __restrict__ src,
                                       __nv_bfloat16* __restrict__ dh,
                                       __nv_bfloat16* __restrict__ dl,
                                       int K, int N, int Kdst, int rowOff)
{
    __shared__ float t[32][33];
    const int k0 = blockIdx.x * 32;
    const int n0 = blockIdx.y * 32;
    const int tx = threadIdx.x, ty = threadIdx.y;

    #pragma unroll
    for (int i = 0; i < 4; ++i) {
        const int kk = k0 + ty + i*8;
        const int nn = n0 + tx;
        t[ty + i*8][tx] = (kk < K && nn < N) ? src[(size_t)kk * N + nn] : 0.0f;
    }
    __syncthreads();
    #pragma unroll
    for (int i = 0; i < 4; ++i) {
        const int nn = n0 + ty + i*8;
        const int kk = k0 + tx;
        const float v = t[tx][ty + i*8];
        const __nv_bfloat16 h = __float2bfloat16(v);
        const float res = v - __bfloat162float(h);
        const size_t di = (size_t)(nn + rowOff) * Kdst + kk;
        dh[di] = h;
        dl[di] = __float2bfloat16(res);
    }
}

// ---------------- RMSNorm fused with bf16 split ----------------
__global__ void rmsnorm_split_kernel(const float* __restrict__ x,
                                     const float* __restrict__ g,
                                     __nv_bfloat16* __restrict__ oh,
                                     __nv_bfloat16* __restrict__ ol)
{
    const int row = blockIdx.x;
    const float4* xr = (const float4*)(x + (size_t)row * DM);
    const float4* gr = (const float4*)g;
    float4 v = xr[threadIdx.x];
    float s = v.x*v.x + v.y*v.y + v.z*v.z + v.w*v.w;
    #pragma unroll
    for (int o = 16; o > 0; o >>= 1) s += __shfl_xor_sync(0xFFFFFFFFu, s, o);
    __shared__ float red[8];
    if ((threadIdx.x & 31) == 0) red[threadIdx.x >> 5] = s;
    __syncthreads();
    float tot = red[0]+red[1]+red[2]+red[3]+red[4]+red[5]+red[6]+red[7];
    float sc = rsqrtf(tot * (1.0f/(float)DM) + 1e-6f);
    float4 gv = gr[threadIdx.x];
    float hv[4];
    hv[0] = v.x * sc * gv.x;
    hv[1] = v.y * sc * gv.y;
    hv[2] = v.z * sc * gv.z;
    hv[3] = v.w * sc * gv.w;
    const size_t base = (size_t)row * DM + threadIdx.x * 4;
    #pragma unroll
    for (int j = 0; j < 4; ++j) {
        const __nv_bfloat16 h = __float2bfloat16(hv[j]);
        oh[base + j] = h;
        ol[base + j] = __float2bfloat16(hv[j] - __bfloat162float(h));
    }
}

// ---------------- q/k L2-norm per head + LOG-SIGMOID(gate), in place ----------------
__global__ void qknorm_kernel(float* __restrict__ q,
                              float* __restrict__ k,
                              float* __restrict__ a)
{
    const int row  = blockIdx.x;
    const int lane = threadIdx.x & 31;
    const int w    = threadIdx.x >> 5;
    float2* qr = (float2*)(q + (size_t)row * DM);
    float2* kr = (float2*)(k + (size_t)row * DM);

    #pragma unroll
    for (int it = 0; it < 2; ++it) {
        const int h = w + it * 8;
        {
            float2 v = qr[h*32 + lane];
            float s = v.x*v.x + v.y*v.y;
            #pragma unroll
            for (int o = 16; o > 0; o >>= 1) s += __shfl_xor_sync(0xFFFFFFFFu, s, o);
            float inv = 1.0f / fmaxf(sqrtf(s), 1e-12f);
            v.x *= inv; v.y *= inv;
            qr[h*32 + lane] = v;
        }
        {
            float2 v = kr[h*32 + lane];
            float s = v.x*v.x + v.y*v.y;
            #pragma unroll
            for (int o = 16; o > 0; o >>= 1) s += __shfl_xor_sync(0xFFFFFFFFu, s, o);
            float inv = 1.0f / fmaxf(sqrtf(s), 1e-12f);
            v.x *= inv; v.y *= inv;
            kr[h*32 + lane] = v;
        }
    }
    float* ar = a + (size_t)row * DM;
    for (int i = threadIdx.x; i < DM; i += 256) {
        float z = ar[i];
        ar[i] = (z >= 0.0f) ? -log1pf(__expf(-z)) : (z - log1pf(__expf(z)));
    }
}

// ---------------- chunked GLA kernels ----------------
__global__ __launch_bounds__(256) void chunk_summary_kernel(
    float* __restrict__ q, float* __restrict__ k,
    const float* __restrict__ v, const float* __restrict__ la,
    float* __restrict__ P, float* __restrict__ Ae)
{
    __shared__ float Ash[CS][64];
    __shared__ float Ks [CS][64];
    __shared__ float Vs [CS][64];

    const int bhc = blockIdx.x;
    const int bh  = bhc >> 4, c = bhc & 15;
    const int b   = bh >> 4,  h = bh & 15;
    const int tid = threadIdx.x;
    const int d   = tid & 63, j0 = tid >> 6;
    const size_t base = ((size_t)(b*1024 + c*CS)) * DM + h*64;

    #pragma unroll
    for (int i = 0; i < 16; ++i) {
        const int j = j0 + 4*i;
        Ash[j][d] = la[base + (size_t)j*DM + d];
    }
    __syncthreads();

    if (tid < 64) {
        float cum = 0.0f, Aj = 1.0f;
        #pragma unroll
        for (int j = 0; j < CS; ++j) {
            cum += Ash[j][tid];
            Aj = __expf(cum);
            Ash[j][tid] = Aj;
        }
        Ae[(size_t)bhc*64 + tid] = Aj;
    }
    __syncthreads();

    #pragma unroll
    for (int i = 0; i < 16; ++i) {
        const int j = j0 + 4*i;
        const size_t off = base + (size_t)j*DM + d;
        const float A = Ash[j][d];
        q[off] = q[off] * A;
        const float kv = __fdividef(k[off], A);
        k[off] = kv;
        Ks[j][d] = kv;
        Vs[j][d] = v[off];
    }
    __syncthreads();

    const int dr = (tid >> 4) << 2;
    const int ec = (tid & 15) << 2;
    float acc[4][4];
    #pragma unroll
    for (int i = 0; i < 4; ++i)
        #pragma unroll
        for (int j = 0; j < 4; ++j) acc[i][j] = 0.0f;

    #pragma unroll 4
    for (int i2 = 0; i2 < CS; ++i2) {
        float kk[4], vv[4];
        *(float4*)kk = *(const float4*)&Ks[i2][dr];
        *(float4*)vv = *(const float4*)&Vs[i2][ec];
        #pragma unroll
        for (int i = 0; i < 4; ++i)
            #pragma unroll
            for (int j = 0; j < 4; ++j)
                acc[i][j] = fmaf(kk[i], vv[j], acc[i][j]);
    }

    float* Pp = P + (size_t)bhc * 4096;
    #pragma unroll
    for (int ii = 0; ii < 4; ++ii) {
        const float aend = Ash[CS-1][dr+ii];
        float4 o4;
        o4.x = acc[ii][0]*aend; o4.y = acc[ii][1]*aend;
        o4.z = acc[ii][2]*aend; o4.w = acc[ii][3]*aend;
        *(float4*)&Pp[(dr+ii)*64 + ec] = o4;
    }
}

__global__ __launch_bounds__(256) void chunk_state_kernel(
    const float* __restrict__ P, const float* __restrict__ Ae,
    float* __restrict__ S)
{
    const int bh  = blockIdx.x;
    const int tid = threadIdx.x;
    const int e   = tid & 63;
    const int d0  = tid >> 6;
    __shared__ float sae[64];

    float s[16];
    #pragma unroll
    for (int i = 0; i < 16; ++i) s[i] = 0.0f;

    for (int c = 0; c < NC; ++c) {
        const size_t idx = (size_t)bh*NC + c;
        if (tid < 64) sae[tid] = Ae[idx*64 + tid];
        __syncthreads();
        const float* Pc = P + idx*4096;
        float*       Sc = S + idx*4096;
        #pragma unroll
        for (int i = 0; i < 16; ++i) {
            const int d = d0 + 4*i;
            Sc[d*64 + e] = s[i];
            s[i] = fmaf(sae[d], s[i], Pc[d*64 + e]);
        }
        __syncthreads();
    }
}

__global__ __launch_bounds__(256) void chunk_output_kernel(
    const float* __restrict__ q, const float* __restrict__ k,
    const float* __restrict__ v, const float* __restrict__ S,
    __nv_bfloat16* __restrict__ oh, __nv_bfloat16* __restrict__ ol)
{
    extern __shared__ float sm3[];
    float (*Qs)[PAD] = (float(*)[PAD])(sm3);
    float (*KT)[PAD] = (float(*)[PAD])(sm3 + 64*PAD);
    float (*Bs)[PAD] = (float(*)[PAD])(sm3 + 2*64*PAD);
    float (*Sc)[PAD] = (float(*)[PAD])(sm3 + 3*64*PAD);

    const int bhc = blockIdx.x;
    const int bh  = bhc >> 4, c = bhc & 15;
    const int b   = bh >> 4,  h = bh & 15;
    const int tid = threadIdx.x;
    const int d   = tid & 63, j0 = tid >> 6;
    const size_t base = ((size_t)(b*1024 + c*CS)) * DM + h*64;
    const float* Sb = S + (size_t)bhc * 4096;

    #pragma unroll
    for (int i = 0; i < 16; ++i) {
        const int j = j0 + 4*i;
        Qs[j][d] = q[base + (size_t)j*DM + d];
        KT[d][j] = k[base + (size_t)j*DM + d];
        Bs[j][d] = Sb[j*64 + d];
    }
    __syncthreads();

    const int tr = (tid >> 4) << 2;
    const int tc = (tid & 15) << 2;

    float acc[4][4], sca[4][4];
    #pragma unroll
    for (int i = 0; i < 4; ++i)
        #pragma unroll
        for (int j = 0; j < 4; ++j) { acc[i][j] = 0.0f; sca[i][j] = 0.0f; }

    #pragma unroll 4
    for (int dd = 0; dd < 64; ++dd) {
        float bv[4], kv[4], av[4];
        *(float4*)bv = *(const float4*)&Bs[dd][tc];
        *(float4*)kv = *(const float4*)&KT[dd][tc];
        #pragma unroll
        for (int i = 0; i < 4; ++i) av[i] = Qs[tr+i][dd];
        #pragma unroll
        for (int i = 0; i < 4; ++i)
            #pragma unroll
            for (int j = 0; j < 4; ++j) {
                acc[i][j] = fmaf(av[i], bv[j], acc[i][j]);
                sca[i][j] = fmaf(av[i], kv[j], sca[i][j]);
            }
    }

    #pragma unroll
    for (int i = 0; i < 4; ++i)
        #pragma unroll
        for (int j = 0; j < 4; ++j)
            Sc[tr+i][tc+j] = ((tc+j) <= (tr+i)) ? sca[i][j] : 0.0f;
    __syncthreads();

    #pragma unroll
    for (int i = 0; i < 16; ++i) {
        const int j = j0 + 4*i;
        Bs[j][d] = v[base + (size_t)j*DM + d];
    }
    __syncthreads();

    #pragma unroll 4
    for (int dd = 0; dd < 64; ++dd) {
        float bv[4], av[4];
        *(float4*)bv = *(const float4*)&Bs[dd][tc];
        #pragma unroll
        for (int i = 0; i < 4; ++i) av[i] = Sc[tr+i][dd];
        #pragma unroll
        for (int i = 0; i < 4; ++i)
            #pragma unroll
            for (int j = 0; j < 4; ++j)
                acc[i][j] = fmaf(av[i], bv[j], acc[i][j]);
    }

    #pragma unroll
    for (int i = 0; i < 4; ++i) {
        const size_t off = base + (size_t)(tr+i)*DM + tc;
        #pragma unroll
        for (int j = 0; j < 4; ++j) {
            const float vvo = acc[i][j];
            const __nv_bfloat16 hh = __float2bfloat16(vvo);
            oh[off + j] = hh;
            ol[off + j] = __float2bfloat16(vvo - __bfloat162float(hh));
        }
    }
}

// ---------------- SwiGLU fused with bf16 split ----------------
__global__ void swiglu_split_kernel(const float* __restrict__ f1,
                                    const float* __restrict__ f2,
                                    __nv_bfloat16* __restrict__ gh,
                                    __nv_bfloat16* __restrict__ gl,
                                    int n4)
{
    int i = blockIdx.x * blockDim.x + threadIdx.x;
    if (i < n4) {
        float4 a = ((const float4*)f1)[i];
        float4 b = ((const float4*)f2)[i];
        float r[4];
        r[0] = a.x / (1.0f + __expf(-a.x)) * b.x;
        r[1] = a.y / (1.0f + __expf(-a.y)) * b.y;
        r[2] = a.z / (1.0f + __expf(-a.z)) * b.z;
        r[3] = a.w / (1.0f + __expf(-a.w)) * b.w;
        #pragma unroll
        for (int j = 0; j < 4; ++j) {
            const __nv_bfloat16 h = __float2bfloat16(r[j]);
            gh[i*4 + j] = h;
            gl[i*4 + j] = __float2bfloat16(r[j] - __bfloat162float(h));
        }
    }
}

// ---------------- host launcher ----------------
extern "C" void kernel_launch(void* const* d_in, const int* in_sizes, int n_in,
                              void* d_out, int out_size)
{
    const float* x   = (const float*)d_in[0];
    const float* Wq  = (const float*)d_in[1];
    const float* Wk  = (const float*)d_in[2];
    const float* Wv  = (const float*)d_in[3];
    const float* Wg  = (const float*)d_in[4];
    const float* Wo  = (const float*)d_in[5];
    const float* w1  = (const float*)d_in[6];
    const float* w2  = (const float*)d_in[7];
    const float* w3  = (const float*)d_in[8];
    const float* gat = (const float*)d_in[9];
    const float* gff = (const float*)d_in[10];
    float* out = (float*)d_out;

    float *pq, *pk, *pv, *pa, *px1, *pf1, *pf2, *pP, *pSs, *pAe;
    __nv_bfloat16 *pxh, *pxl, *pf1h, *pf1l;
    __nv_bfloat16 *pWTh, *pWTl, *pWoTh, *pWoTl, *pW12Th, *pW12Tl, *pW3Th, *pW3Tl;
    cudaGetSymbolAddress((void**)&pq,  g_q);
    cudaGetSymbolAddress((void**)&pk,  g_k);
    cudaGetSymbolAddress((void**)&pv,  g_v);
    cudaGetSymbolAddress((void**)&pa,  g_a);
    cudaGetSymbolAddress((void**)&px1, g_x1);
    cudaGetSymbolAddress((void**)&pf1, g_f1);
    cudaGetSymbolAddress((void**)&pf2, g_f2);
    cudaGetSymbolAddress((void**)&pP,  g_P);
    cudaGetSymbolAddress((void**)&pSs, g_Ss);
    cudaGetSymbolAddress((void**)&pAe, g_Ae);
    cudaGetSymbolAddress((void**)&pxh, g_xh);
    cudaGetSymbolAddress((void**)&pxl, g_xl);
    cudaGetSymbolAddress((void**)&pf1h, g_f1h);
    cudaGetSymbolAddress((void**)&pf1l, g_f1l);
    cudaGetSymbolAddress((void**)&pWTh, g_WTh);
    cudaGetSymbolAddress((void**)&pWTl, g_WTl);
    cudaGetSymbolAddress((void**)&pWoTh, g_WoTh);
    cudaGetSymbolAddress((void**)&pWoTl, g_WoTl);
    cudaGetSymbolAddress((void**)&pW12Th, g_W12Th);
    cudaGetSymbolAddress((void**)&pW12Tl, g_W12Tl);
    cudaGetSymbolAddress((void**)&pW3Th, g_W3Th);
    cudaGetSymbolAddress((void**)&pW3Tl, g_W3Tl);

    static bool attr_done = false;
    if (!attr_done) {
        cudaFuncSetAttribute(chunk_output_kernel,
                             cudaFuncAttributeMaxDynamicSharedMemorySize,
                             4 * 64 * PAD * (int)sizeof(float));
        cudaFuncSetAttribute(bfgemm_kernel,
                             cudaFuncAttributeMaxDynamicSharedMemorySize,
                             GEMM_SMEM);
        attr_done = true;
    }

    dim3 tb(32, 8);
    // 0) transpose + split all weights
    transpose_split_kernel<<<dim3(32, 32), tb>>>(Wq, pWTh, pWTl, 1024, 1024, 1024, 0);
    transpose_split_kernel<<<dim3(32, 32), tb>>>(Wk, pWTh, pWTl, 1024, 1024, 1024, 1024);
    transpose_split_kernel<<<dim3(32, 32), tb>>>(Wv, pWTh, pWTl, 1024, 1024, 1024, 2048);
    transpose_split_kernel<<<dim3(32, 32), tb>>>(Wg, pWTh, pWTl, 1024, 1024, 1024, 3072);
    transpose_split_kernel<<<dim3(32, 32), tb>>>(Wo, pWoTh, pWoTl, 1024, 1024, 1024, 0);
    transpose_split_kernel<<<dim3(32, DFFP/32), tb>>>(w1, pW12Th, pW12Tl, 1024, DFF, 1024, 0);
    transpose_split_kernel<<<dim3(32, DFFP/32), tb>>>(w2, pW12Th, pW12Tl, 1024, DFF, 1024, DFFP);
    transpose_split_kernel<<<dim3(DFFP/32, 32), tb>>>(w3, pW3Th, pW3Tl, DFF, 1024, DFFP, 0);

    // 1) h = rmsnorm(x, g_attn), split to bf16 hi/lo
    rmsnorm_split_kernel<<<BT, 256>>>(x, gat, pxh, pxl);

    // 2) q,k,v,gate = h @ {Wq,Wk,Wv,Wg}  (one N=4096 GEMM)
    bfgemm_kernel<<<dim3(4096/128, BT/128), 256, GEMM_SMEM>>>(
        pxh, pxl, pWTh, pWTl, pq, pk, pv, pa, nullptr, 1024, 1024);

    // 3) l2norm(q), l2norm(k), log-sigmoid(gate)
    qknorm_kernel<<<BT, 256>>>(pq, pk, pa);

    // 4) chunked GLA -> o (split bf16)
    chunk_summary_kernel<<<NBHC, 256>>>(pq, pk, pv, pa, pP, pAe);
    chunk_state_kernel  <<<32,   256>>>(pP, pAe, pSs);
    chunk_output_kernel <<<NBHC, 256, 4*64*PAD*(int)sizeof(float)>>>(pq, pk, pv, pSs, pxh, pxl);

    // 5) x1 = x + o @ Wo
    bfgemm_kernel<<<dim3(1024/128, BT/128), 256, GEMM_SMEM>>>(
        pxh, pxl, pWoTh, pWoTl, px1, nullptr, nullptr, nullptr, x, 1024, 1024);

    // 6) h = rmsnorm(x1, g_ffn), split
    rmsnorm_split_kernel<<<BT, 256>>>(px1, gff, pxh, pxl);

    // 7) f1 = h @ w1 ; f2 = h @ w2   (one N=5632 GEMM, padded)
    bfgemm_kernel<<<dim3(2*DFFP/128, BT/128), 256, GEMM_SMEM>>>(
        pxh, pxl, pW12Th, pW12Tl, pf1, pf2, nullptr, nullptr, nullptr, 1024, DFFP);

    // 8) gated = silu(f1) * f2, split to bf16
    {
        const int n4 = BT * DFFP / 4;
        swiglu_split_kernel<<<(n4 + 255)/256, 256>>>(pf1, pf2, pf1h, pf1l, n4);
    }

    // 9) out = x1 + gated @ w3  (K = 2816 padded)
    bfgemm_kernel<<<dim3(1024/128, BT/128), 256, GEMM_SMEM>>>(
        pf1h, pf1l, pW3Th, pW3Tl, out, nullptr, nullptr, nullptr, px1, DFFP, 1024);
}

// round 9
// speedup vs baseline: 2.3038x; 1.0128x over previous
#include <cuda_runtime.h>
#include <cuda_bf16.h>
#include <math.h>

#define BT   2048     // B*T
#define DM   1024     // d_model
#define NH   16
#define DKV  64
#define DFF  2736
#define DFFP 2816     // DFF padded to multiple of 128
#define NC   16       // chunks per sequence
#define CS   64       // chunk size
#define NBHC 512      // B*H*NC
#define PAD  68       // smem row stride (floats) for chunk_output

typedef unsigned long long u64;
typedef unsigned int u32;

// ---------------- scratch (static device globals; no allocation) ----------------
__device__ float g_q [BT*DM];
__device__ float g_k [BT*DM];
__device__ float g_v [BT*DM];
__device__ float g_a [BT*DM];
__device__ float g_x1[BT*DM];
__device__ float g_f1[BT*DFFP];
__device__ float g_f2[BT*DFFP];
__device__ float g_P [NBHC*4096];
__device__ float g_Ss[NBHC*4096];
__device__ float g_Ae[NBHC*64];

// bf16 split buffers
__device__ __nv_bfloat16 g_xh [BT*DM];
__device__ __nv_bfloat16 g_xl [BT*DM];
__device__ __nv_bfloat16 g_f1h[BT*DFFP];
__device__ __nv_bfloat16 g_f1l[BT*DFFP];
__device__ __nv_bfloat16 g_WTh [4096*1024];    // QKVG weights transposed [4096][1024]
__device__ __nv_bfloat16 g_WTl [4096*1024];
__device__ __nv_bfloat16 g_WoTh[1024*1024];
__device__ __nv_bfloat16 g_WoTl[1024*1024];
__device__ __nv_bfloat16 g_W12Th[2*DFFP*1024]; // [5632][1024]
__device__ __nv_bfloat16 g_W12Tl[2*DFFP*1024];
__device__ __nv_bfloat16 g_W3Th[1024*DFFP];    // [1024][2816]
__device__ __nv_bfloat16 g_W3Tl[1024*DFFP];

// ---------------- PTX helpers (all sm_80-era, legal on compute_103) ----------------
__device__ __forceinline__ u32 s2u(const void* p) {
    u32 a;
    asm("{ .reg .u64 t; cvta.to.shared.u64 t, %1; cvt.u32.u64 %0, t; }" : "=r"(a) : "l"(p));
    return a;
}
__device__ __forceinline__ void ldsm_x4(u32* r, u32 addr) {
    asm volatile("ldmatrix.sync.aligned.m8n8.x4.shared.b16 {%0,%1,%2,%3}, [%4];"
        : "=r"(r[0]), "=r"(r[1]), "=r"(r[2]), "=r"(r[3]) : "r"(addr));
}
__device__ __forceinline__ void mma16816(float* c, const u32* a, const u32* b) {
    asm volatile(
        "mma.sync.aligned.m16n8k16.row.col.f32.bf16.bf16.f32 "
        "{%0,%1,%2,%3}, {%4,%5,%6,%7}, {%8,%9}, {%0,%1,%2,%3};"
        : "+f"(c[0]), "+f"(c[1]), "+f"(c[2]), "+f"(c[3])
        : "r"(a[0]), "r"(a[1]), "r"(a[2]), "r"(a[3]), "r"(b[0]), "r"(b[1]));
}
__device__ __forceinline__ void cp16(u32 dst, const void* src) {
    asm volatile("cp.async.cg.shared.global [%0], [%1], 16;" :: "r"(dst), "l"(src));
}
__device__ __forceinline__ void cp_commit() {
    asm volatile("cp.async.commit_group;" ::: "memory");
}
template<int N>
__device__ __forceinline__ void cp_wait() {
    asm volatile("cp.async.wait_group %0;" :: "n"(N) : "memory");
}

// ---------------- bf16-split warp-MMA GEMM, cp.async double-buffered ----------------
// C[M,Ntot] = A[M,K] @ W[K,Ntot] (+R); A,W pre-split to bf16 hi/lo,
// W pre-transposed to [Ntot][K]. 128x128 CTA tile, BK=64, 256 threads = 8 warps
// (2m x 4n), warp tile 64x32. Two smem stages pipelined via cp.async.
#define RSB 144                    // smem row stride bytes (128B data + 16B pad)
#define TILE_BYTES (128*RSB)       // 18432
#define STAGE_BYTES (4*TILE_BYTES) // 73728
#define GEMM_SMEM (2*STAGE_BYTES)  // 147456

__global__ __launch_bounds__(256) void bfgemm_kernel(
    const __nv_bfloat16* __restrict__ Ah, const __nv_bfloat16* __restrict__ Al,
    const __nv_bfloat16* __restrict__ Bh, const __nv_bfloat16* __restrict__ Bl,
    float* C0, float* C1, float* C2, float* C3,
    const float* __restrict__ R,
    int K, int Nper)
{
    extern __shared__ char sm[];

    const int tid  = threadIdx.x;
    const int lane = tid & 31;
    const int wid  = tid >> 5;
    const int wr   = wid >> 2;     // 0..1  (m)
    const int wc   = wid & 3;      // 0..3  (n)
    const int bn = blockIdx.x * 128;
    const int bm = blockIdx.y * 128;

    const int lrow  = tid >> 1;    // 0..127
    const int lhalf = tid & 1;     // which 64B half of the 128B row

    float acc[4][4][4];
    #pragma unroll
    for (int i = 0; i < 4; ++i)
        #pragma unroll
        for (int j = 0; j < 4; ++j)
            #pragma unroll
            for (int q = 0; q < 4; ++q) acc[i][j][q] = 0.0f;

    const char* gAh = (const char*)(Ah + (size_t)(bm + lrow) * K) + lhalf * 64;
    const char* gAl = (const char*)(Al + (size_t)(bm + lrow) * K) + lhalf * 64;
    const char* gBh = (const char*)(Bh + (size_t)(bn + lrow) * K) + lhalf * 64;
    const char* gBl = (const char*)(Bl + (size_t)(bn + lrow) * K) + lhalf * 64;
    const u32 so = (u32)lrow * RSB + (u32)lhalf * 64;
    const u32 uS = s2u(sm);

    const int niter = K >> 6;

    // issue loads for stage `it` into buffer it&1
    auto issue = [&](int it) {
        const int kb = it * 128;   // byte offset into bf16 row
        const u32 ub = uS + (u32)(it & 1) * STAGE_BYTES + so;
        #pragma unroll
        for (int i = 0; i < 4; ++i) {
            cp16(ub                + i*16, gAh + kb + i*16);
            cp16(ub +   TILE_BYTES + i*16, gAl + kb + i*16);
            cp16(ub + 2*TILE_BYTES + i*16, gBh + kb + i*16);
            cp16(ub + 3*TILE_BYTES + i*16, gBl + kb + i*16);
        }
        cp_commit();
    };

    issue(0);

    for (int it = 0; it < niter; ++it) {
        if (it + 1 < niter) { issue(it + 1); cp_wait<1>(); }
        else                { cp_wait<0>(); }
        __syncthreads();

        const u32 ubuf = uS + (u32)(it & 1) * STAGE_BYTES;
        const u32 uAh = ubuf;
        const u32 uAl = ubuf + TILE_BYTES;
        const u32 uBh = ubuf + 2*TILE_BYTES;
        const u32 uBl = ubuf + 3*TILE_BYTES;

        #pragma unroll
        for (int ks = 0; ks < 4; ++ks) {
            const u32 coff = (u32)ks * 32 + ((u32)(lane >> 4)) * 16;
            const u32 rsel = (u32)(lane & 15);
            u32 ah[4][4], al[4][4], bh[4][2], bl[4][2];

            #pragma unroll
            for (int mi = 0; mi < 4; ++mi) {
                const u32 ra = (u32)(wr*64 + mi*16) * RSB + rsel * RSB + coff;
                ldsm_x4(ah[mi], uAh + ra);
                ldsm_x4(al[mi], uAl + ra);
            }
            #pragma unroll
            for (int jj = 0; jj < 2; ++jj) {
                const u32 rb = (u32)(wc*32 + jj*16) * RSB + rsel * RSB + coff;
                u32 t[4];
                ldsm_x4(t, uBh + rb);
                bh[jj*2+0][0] = t[0]; bh[jj*2+0][1] = t[2];
                bh[jj*2+1][0] = t[1]; bh[jj*2+1][1] = t[3];
                ldsm_x4(t, uBl + rb);
                bl[jj*2+0][0] = t[0]; bl[jj*2+0][1] = t[2];
                bl[jj*2+1][0] = t[1]; bl[jj*2+1][1] = t[3];
            }

            #pragma unroll
            for (int mi = 0; mi < 4; ++mi)
                #pragma unroll
                for (int nj = 0; nj < 4; ++nj) {
                    mma16816(acc[mi][nj], ah[mi], bh[nj]);
                    mma16816(acc[mi][nj], ah[mi], bl[nj]);
                    mma16816(acc[mi][nj], al[mi], bh[nj]);
                }
        }
        __syncthreads();
    }

    // epilogue: fragment c0,c1 -> row g; c2,c3 -> row g+8; cols 2t,2t+1
    const int arr = bn / Nper;
    float* C = (arr == 0) ? C0 : (arr == 1) ? C1 : (arr == 2) ? C2 : C3;
    const int cb = bn - arr * Nper;

    #pragma unroll
    for (int mi = 0; mi < 4; ++mi) {
        const int r0 = bm + wr*64 + mi*16 + (lane >> 2);
        #pragma unroll
        for (int nj = 0; nj < 4; ++nj) {
            const int col = cb + wc*32 + nj*8 + (lane & 3)*2;
            float2 v0 = make_float2(acc[mi][nj][0], acc[mi][nj][1]);
            float2 v1 = make_float2(acc[mi][nj][2], acc[mi][nj][3]);
            if (R) {
                const float2 q0 = *(const float2*)(R + (size_t)r0 * Nper + col);
                const float2 q1 = *(const float2*)(R + (size_t)(r0+8) * Nper + col);
                v0.x += q0.x; v0.y += q0.y;
                v1.x += q1.x; v1.y += q1.y;
            }
            *(float2*)(C + (size_t)r0     * Nper + col) = v0;
            *(float2*)(C + (size_t)(r0+8) * Nper + col) = v1;
        }
    }
}

// ---------------- transpose + bf16 split: W[K,N] -> WT_hi/lo[N(+off)][Kdst] ----------
__global__ void transpose_split_kernel(const float* __restrict__ src,
                                       __nv_bfloat16* __restrict__ dh,
                                       __nv_bfloat16* __restrict__ dl,
                                       int K, int N, int Kdst, int rowOff)
{
    __shared__ float t[32][33];
    const int k0 = blockIdx.x * 32;
    const int n0 = blockIdx.y * 32;
    const int tx = threadIdx.x, ty = threadIdx.y;

    #pragma unroll
    for (int i = 0; i < 4; ++i) {
        const int kk = k0 + ty + i*8;
        const int nn = n0 + tx;
        t[ty + i*8][tx] = (kk < K && nn < N) ? src[(size_t)kk * N + nn] : 0.0f;
    }
    __syncthreads();
    #pragma unroll
    for (int i = 0; i < 4; ++i) {
        const int nn = n0 + ty + i*8;
        const int kk = k0 + tx;
        const float v = t[tx][ty + i*8];
        const __nv_bfloat16 h = __float2bfloat16(v);
        const float res = v - __bfloat162float(h);
        const size_t di = (size_t)(nn + rowOff) * Kdst + kk;
        dh[di] = h;
        dl[di] = __float2bfloat16(res);
    }
}

// ---------------- RMSNorm fused with bf16 split ----------------
__global__ void rmsnorm_split_kernel(const float* __restrict__ x,
                                     const float* __restrict__ g,
                                     __nv_bfloat16* __restrict__ oh,
                                     __nv_bfloat16* __restrict__ ol)
{
    const int row = blockIdx.x;
    const float4* xr = (const float4*)(x + (size_t)row * DM);
    const float4* gr = (const float4*)g;
    float4 v = xr[threadIdx.x];
    float s = v.x*v.x + v.y*v.y + v.z*v.z + v.w*v.w;
    #pragma unroll
    for (int o = 16; o > 0; o >>= 1) s += __shfl_xor_sync(0xFFFFFFFFu, s, o);
    __shared__ float red[8];
    if ((threadIdx.x & 31) == 0) red[threadIdx.x >> 5] = s;
    __syncthreads();
    float tot = red[0]+red[1]+red[2]+red[3]+red[4]+red[5]+red[6]+red[7];
    float sc = rsqrtf(tot * (1.0f/(float)DM) + 1e-6f);
    float4 gv = gr[threadIdx.x];
    float hv[4];
    hv[0] = v.x * sc * gv.x;
    hv[1] = v.y * sc * gv.y;
    hv[2] = v.z * sc * gv.z;
    hv[3] = v.w * sc * gv.w;
    const size_t base = (size_t)row * DM + threadIdx.x * 4;
    #pragma unroll
    for (int j = 0; j < 4; ++j) {
        const __nv_bfloat16 h = __float2bfloat16(hv[j]);
        oh[base + j] = h;
        ol[base + j] = __float2bfloat16(hv[j] - __bfloat162float(h));
    }
}

// ---------------- q/k L2-norm per head + LOG-SIGMOID(gate), in place ----------------
__global__ void qknorm_kernel(float* __restrict__ q,
                              float* __restrict__ k,
                              float* __restrict__ a)
{
    const int row  = blockIdx.x;
    const int lane = threadIdx.x & 31;
    const int w    = threadIdx.x >> 5;
    float2* qr = (float2*)(q + (size_t)row * DM);
    float2* kr = (float2*)(k + (size_t)row * DM);

    #pragma unroll
    for (int it = 0; it < 2; ++it) {
        const int h = w + it * 8;
        {
            float2 v = qr[h*32 + lane];
            float s = v.x*v.x + v.y*v.y;
            #pragma unroll
            for (int o = 16; o > 0; o >>= 1) s += __shfl_xor_sync(0xFFFFFFFFu, s, o);
            float inv = 1.0f / fmaxf(sqrtf(s), 1e-12f);
            v.x *= inv; v.y *= inv;
            qr[h*32 + lane] = v;
        }
        {
            float2 v = kr[h*32 + lane];
            float s = v.x*v.x + v.y*v.y;
            #pragma unroll
            for (int o = 16; o > 0; o >>= 1) s += __shfl_xor_sync(0xFFFFFFFFu, s, o);
            float inv = 1.0f / fmaxf(sqrtf(s), 1e-12f);
            v.x *= inv; v.y *= inv;
            kr[h*32 + lane] = v;
        }
    }
    float* ar = a + (size_t)row * DM;
    for (int i = threadIdx.x; i < DM; i += 256) {
        float z = ar[i];
        ar[i] = (z >= 0.0f) ? -log1pf(__expf(-z)) : (z - log1pf(__expf(z)));
    }
}

// ---------------- chunked GLA kernels ----------------
__global__ __launch_bounds__(256) void chunk_summary_kernel(
    float* __restrict__ q, float* __restrict__ k,
    const float* __restrict__ v, const float* __restrict__ la,
    float* __restrict__ P, float* __restrict__ Ae)
{
    __shared__ float Ash[CS][64];
    __shared__ float Ks [CS][64];
    __shared__ float Vs [CS][64];

    const int bhc = blockIdx.x;
    const int bh  = bhc >> 4, c = bhc & 15;
    const int b   = bh >> 4,  h = bh & 15;
    const int tid = threadIdx.x;
    const int d   = tid & 63, j0 = tid >> 6;
    const size_t base = ((size_t)(b*1024 + c*CS)) * DM + h*64;

    #pragma unroll
    for (int i = 0; i < 16; ++i) {
        const int j = j0 + 4*i;
        Ash[j][d] = la[base + (size_t)j*DM + d];
    }
    __syncthreads();

    if (tid < 64) {
        float cum = 0.0f, Aj = 1.0f;
        #pragma unroll
        for (int j = 0; j < CS; ++j) {
            cum += Ash[j][tid];
            Aj = __expf(cum);
            Ash[j][tid] = Aj;
        }
        Ae[(size_t)bhc*64 + tid] = Aj;
    }
    __syncthreads();

    #pragma unroll
    for (int i = 0; i < 16; ++i) {
        const int j = j0 + 4*i;
        const size_t off = base + (size_t)j*DM + d;
        const float A = Ash[j][d];
        q[off] = q[off] * A;
        const float kv = __fdividef(k[off], A);
        k[off] = kv;
        Ks[j][d] = kv;
        Vs[j][d] = v[off];
    }
    __syncthreads();

    const int dr = (tid >> 4) << 2;
    const int ec = (tid & 15) << 2;
    float acc[4][4];
    #pragma unroll
    for (int i = 0; i < 4; ++i)
        #pragma unroll
        for (int j = 0; j < 4; ++j) acc[i][j] = 0.0f;

    #pragma unroll 4
    for (int i2 = 0; i2 < CS; ++i2) {
        float kk[4], vv[4];
        *(float4*)kk = *(const float4*)&Ks[i2][dr];
        *(float4*)vv = *(const float4*)&Vs[i2][ec];
        #pragma unroll
        for (int i = 0; i < 4; ++i)
            #pragma unroll
            for (int j = 0; j < 4; ++j)
                acc[i][j] = fmaf(kk[i], vv[j], acc[i][j]);
    }

    float* Pp = P + (size_t)bhc * 4096;
    #pragma unroll
    for (int ii = 0; ii < 4; ++ii) {
        const float aend = Ash[CS-1][dr+ii];
        float4 o4;
        o4.x = acc[ii][0]*aend; o4.y = acc[ii][1]*aend;
        o4.z = acc[ii][2]*aend; o4.w = acc[ii][3]*aend;
        *(float4*)&Pp[(dr+ii)*64 + ec] = o4;
    }
}

__global__ __launch_bounds__(256) void chunk_state_kernel(
    const float* __restrict__ P, const float* __restrict__ Ae,
    float* __restrict__ S)
{
    const int bh  = blockIdx.x;
    const int tid = threadIdx.x;
    const int e   = tid & 63;
    const int d0  = tid >> 6;
    __shared__ float sae[64];

    float s[16];
    #pragma unroll
    for (int i = 0; i < 16; ++i) s[i] = 0.0f;

    for (int c = 0; c < NC; ++c) {
        const size_t idx = (size_t)bh*NC + c;
        if (tid < 64) sae[tid] = Ae[idx*64 + tid];
        __syncthreads();
        const float* Pc = P + idx*4096;
        float*       Sc = S + idx*4096;
        #pragma unroll
        for (int i = 0; i < 16; ++i) {
            const int d = d0 + 4*i;
            Sc[d*64 + e] = s[i];
            s[i] = fmaf(sae[d], s[i], Pc[d*64 + e]);
        }
        __syncthreads();
    }
}

__global__ __launch_bounds__(256) void chunk_output_kernel(
    const float* __restrict__ q, const float* __restrict__ k,
    const float* __restrict__ v, const float* __restrict__ S,
    __nv_bfloat16* __restrict__ oh, __nv_bfloat16* __restrict__ ol)
{
    extern __shared__ float sm3[];
    float (*Qs)[PAD] = (float(*)[PAD])(sm3);
    float (*KT)[PAD] = (float(*)[PAD])(sm3 + 64*PAD);
    float (*Bs)[PAD] = (float(*)[PAD])(sm3 + 2*64*PAD);
    float (*Sc)[PAD] = (float(*)[PAD])(sm3 + 3*64*PAD);

    const int bhc = blockIdx.x;
    const int bh  = bhc >> 4, c = bhc & 15;
    const int b   = bh >> 4,  h = bh & 15;
    const int tid = threadIdx.x;
    const int d   = tid & 63, j0 = tid >> 6;
    const size_t base = ((size_t)(b*1024 + c*CS)) * DM + h*64;
    const float* Sb = S + (size_t)bhc * 4096;

    #pragma unroll
    for (int i = 0; i < 16; ++i) {
        const int j = j0 + 4*i;
        Qs[j][d] = q[base + (size_t)j*DM + d];
        KT[d][j] = k[base + (size_t)j*DM + d];
        Bs[j][d] = Sb[j*64 + d];
    }
    __syncthreads();

    const int tr = (tid >> 4) << 2;
    const int tc = (tid & 15) << 2;

    float acc[4][4], sca[4][4];
    #pragma unroll
    for (int i = 0; i < 4; ++i)
        #pragma unroll
        for (int j = 0; j < 4; ++j) { acc[i][j] = 0.0f; sca[i][j] = 0.0f; }

    #pragma unroll 4
    for (int dd = 0; dd < 64; ++dd) {
        float bv[4], kv[4], av[4];
        *(float4*)bv = *(const float4*)&Bs[dd][tc];
        *(float4*)kv = *(const float4*)&KT[dd][tc];
        #pragma unroll
        for (int i = 0; i < 4; ++i) av[i] = Qs[tr+i][dd];
        #pragma unroll
        for (int i = 0; i < 4; ++i)
            #pragma unroll
            for (int j = 0; j < 4; ++j) {
                acc[i][j] = fmaf(av[i], bv[j], acc[i][j]);
                sca[i][j] = fmaf(av[i], kv[j], sca[i][j]);
            }
    }

    #pragma unroll
    for (int i = 0; i < 4; ++i)
        #pragma unroll
        for (int j = 0; j < 4; ++j)
            Sc[tr+i][tc+j] = ((tc+j) <= (tr+i)) ? sca[i][j] : 0.0f;
    __syncthreads();

    #pragma unroll
    for (int i = 0; i < 16; ++i) {
        const int j = j0 + 4*i;
        Bs[j][d] = v[base + (size_t)j*DM + d];
    }
    __syncthreads();

    #pragma unroll 4
    for (int dd = 0; dd < 64; ++dd) {
        float bv[4], av[4];
        *(float4*)bv = *(const float4*)&Bs[dd][tc];
        #pragma unroll
        for (int i = 0; i < 4; ++i) av[i] = Sc[tr+i][dd];
        #pragma unroll
        for (int i = 0; i < 4; ++i)
            #pragma unroll
            for (int j = 0; j < 4; ++j)
                acc[i][j] = fmaf(av[i], bv[j], acc[i][j]);
    }

    #pragma unroll
    for (int i = 0; i < 4; ++i) {
        const size_t off = base + (size_t)(tr+i)*DM + tc;
        #pragma unroll
        for (int j = 0; j < 4; ++j) {
            const float vvo = acc[i][j];
            const __nv_bfloat16 hh = __float2bfloat16(vvo);
            oh[off + j] = hh;
            ol[off + j] = __float2bfloat16(vvo - __bfloat162float(hh));
        }
    }
}

// ---------------- SwiGLU fused with bf16 split ----------------
__global__ void swiglu_split_kernel(const float* __restrict__ f1,
                                    const float* __restrict__ f2,
                                    __nv_bfloat16* __restrict__ gh,
                                    __nv_bfloat16* __restrict__ gl,
                                    int n4)
{
    int i = blockIdx.x * blockDim.x + threadIdx.x;
    if (i < n4) {
        float4 a = ((const float4*)f1)[i];
        float4 b = ((const float4*)f2)[i];
        float r[4];
        r[0] = a.x / (1.0f + __expf(-a.x)) * b.x;
        r[1] = a.y / (1.0f + __expf(-a.y)) * b.y;
        r[2] = a.z / (1.0f + __expf(-a.z)) * b.z;
        r[3] = a.w / (1.0f + __expf(-a.w)) * b.w;
        #pragma unroll
        for (int j = 0; j < 4; ++j) {
            const __nv_bfloat16 h = __float2bfloat16(r[j]);
            gh[i*4 + j] = h;
            gl[i*4 + j] = __float2bfloat16(r[j] - __bfloat162float(h));
        }
    }
}

// ---------------- host launcher ----------------
extern "C" void kernel_launch(void* const* d_in, const int* in_sizes, int n_in,
                              void* d_out, int out_size)
{
    const float* x   = (const float*)d_in[0];
    const float* Wq  = (const float*)d_in[1];
    const float* Wk  = (const float*)d_in[2];
    const float* Wv  = (const float*)d_in[3];
    const float* Wg  = (const float*)d_in[4];
    const float* Wo  = (const float*)d_in[5];
    const float* w1  = (const float*)d_in[6];
    const float* w2  = (const float*)d_in[7];
    const float* w3  = (const float*)d_in[8];
    const float* gat = (const float*)d_in[9];
    const float* gff = (const float*)d_in[10];
    float* out = (float*)d_out;

    float *pq, *pk, *pv, *pa, *px1, *pf1, *pf2, *pP, *pSs, *pAe;
    __nv_bfloat16 *pxh, *pxl, *pf1h, *pf1l;
    __nv_bfloat16 *pWTh, *pWTl, *pWoTh, *pWoTl, *pW12Th, *pW12Tl, *pW3Th, *pW3Tl;
    cudaGetSymbolAddress((void**)&pq,  g_q);
    cudaGetSymbolAddress((void**)&pk,  g_k);
    cudaGetSymbolAddress((void**)&pv,  g_v);
    cudaGetSymbolAddress((void**)&pa,  g_a);
    cudaGetSymbolAddress((void**)&px1, g_x1);
    cudaGetSymbolAddress((void**)&pf1, g_f1);
    cudaGetSymbolAddress((void**)&pf2, g_f2);
    cudaGetSymbolAddress((void**)&pP,  g_P);
    cudaGetSymbolAddress((void**)&pSs, g_Ss);
    cudaGetSymbolAddress((void**)&pAe, g_Ae);
    cudaGetSymbolAddress((void**)&pxh, g_xh);
    cudaGetSymbolAddress((void**)&pxl, g_xl);
    cudaGetSymbolAddress((void**)&pf1h, g_f1h);
    cudaGetSymbolAddress((void**)&pf1l, g_f1l);
    cudaGetSymbolAddress((void**)&pWTh, g_WTh);
    cudaGetSymbolAddress((void**)&pWTl, g_WTl);
    cudaGetSymbolAddress((void**)&pWoTh, g_WoTh);
    cudaGetSymbolAddress((void**)&pWoTl, g_WoTl);
    cudaGetSymbolAddress((void**)&pW12Th, g_W12Th);
    cudaGetSymbolAddress((void**)&pW12Tl, g_W12Tl);
    cudaGetSymbolAddress((void**)&pW3Th, g_W3Th);
    cudaGetSymbolAddress((void**)&pW3Tl, g_W3Tl);

    static bool attr_done = false;
    if (!attr_done) {
        cudaFuncSetAttribute(chunk_output_kernel,
                             cudaFuncAttributeMaxDynamicSharedMemorySize,
                             4 * 64 * PAD * (int)sizeof(float));
        cudaFuncSetAttribute(bfgemm_kernel,
                             cudaFuncAttributeMaxDynamicSharedMemorySize,
                             GEMM_SMEM);
        attr_done = true;
    }

    dim3 tb(32, 8);
    // 0) transpose + split all weights
    transpose_split_kernel<<<dim3(32, 32), tb>>>(Wq, pWTh, pWTl, 1024, 1024, 1024, 0);
    transpose_split_kernel<<<dim3(32, 32), tb>>>(Wk, pWTh, pWTl, 1024, 1024, 1024, 1024);
    transpose_split_kernel<<<dim3(32, 32), tb>>>(Wv, pWTh, pWTl, 1024, 1024, 1024, 2048);
    transpose_split_kernel<<<dim3(32, 32), tb>>>(Wg, pWTh, pWTl, 1024, 1024, 1024, 3072);
    transpose_split_kernel<<<dim3(32, 32), tb>>>(Wo, pWoTh, pWoTl, 1024, 1024, 1024, 0);
    transpose_split_kernel<<<dim3(32, DFFP/32), tb>>>(w1, pW12Th, pW12Tl, 1024, DFF, 1024, 0);
    transpose_split_kernel<<<dim3(32, DFFP/32), tb>>>(w2, pW12Th, pW12Tl, 1024, DFF, 1024, DFFP);
    transpose_split_kernel<<<dim3(DFFP/32, 32), tb>>>(w3, pW3Th, pW3Tl, DFF, 1024, DFFP, 0);

    // 1) h = rmsnorm(x, g_attn), split to bf16 hi/lo
    rmsnorm_split_kernel<<<BT, 256>>>(x, gat, pxh, pxl);

    // 2) q,k,v,gate = h @ {Wq,Wk,Wv,Wg}  (one N=4096 GEMM)
    bfgemm_kernel<<<dim3(4096/128, BT/128), 256, GEMM_SMEM>>>(
        pxh, pxl, pWTh, pWTl, pq, pk, pv, pa, nullptr, 1024, 1024);

    // 3) l2norm(q), l2norm(k), log-sigmoid(gate)
    qknorm_kernel<<<BT, 256>>>(pq, pk, pa);

    // 4) chunked GLA -> o (split bf16)
    chunk_summary_kernel<<<NBHC, 256>>>(pq, pk, pv, pa, pP, pAe);
    chunk_state_kernel  <<<32,   256>>>(pP, pAe, pSs);
    chunk_output_kernel <<<NBHC, 256, 4*64*PAD*(int)sizeof(float)>>>(pq, pk, pv, pSs, pxh, pxl);

    // 5) x1 = x + o @ Wo
    bfgemm_kernel<<<dim3(1024/128, BT/128), 256, GEMM_SMEM>>>(
        pxh, pxl, pWoTh, pWoTl, px1, nullptr, nullptr, nullptr, x, 1024, 1024);

    // 6) h = rmsnorm(x1, g_ffn), split
    rmsnorm_split_kernel<<<BT, 256>>>(px1, gff, pxh, pxl);

    // 7) f1 = h @ w1 ; f2 = h @ w2   (one N=5632 GEMM, padded)
    bfgemm_kernel<<<dim3(2*DFFP/128, BT/128), 256, GEMM_SMEM>>>(
        pxh, pxl, pW12Th, pW12Tl, pf1, pf2, nullptr, nullptr, nullptr, 1024, DFFP);

    // 8) gated = silu(f1) * f2, split to bf16
    {
        const int n4 = BT * DFFP / 4;
        swiglu_split_kernel<<<(n4 + 255)/256, 256>>>(pf1, pf2, pf1h, pf1l, n4);
    }

    // 9) out = x1 + gated @ w3  (K = 2816 padded)
    bfgemm_kernel<<<dim3(1024/128, BT/128), 256, GEMM_SMEM>>>(
        pf1h, pf1l, pW3Th, pW3Tl, out, nullptr, nullptr, nullptr, px1, DFFP, 1024);
}

// round 11
// speedup vs baseline: 3.5484x; 1.5403x over previous
#include <cuda_runtime.h>
#include <cuda_bf16.h>
#include <math.h>

#define BT   2048     // B*T
#define DM   1024     // d_model
#define NH   16
#define DKV  64
#define DFF  2736
#define DFFP 2816     // DFF padded to multiple of 128
#define NC   16       // chunks per sequence
#define CS   64       // chunk size
#define NBHC 512      // B*H*NC
#define PAD  68       // smem row stride (floats) for chunk_output

typedef unsigned long long u64;
typedef unsigned int u32;

// ---------------- scratch (static device globals; no allocation) ----------------
__device__ float g_q [BT*DM];
__device__ float g_k [BT*DM];
__device__ float g_v [BT*DM];
__device__ float g_a [BT*DM];
__device__ float g_x1[BT*DM];
__device__ float g_f1[BT*DFFP];
__device__ float g_f2[BT*DFFP];
__device__ float g_P [NBHC*4096];
__device__ float g_Ss[NBHC*4096];
__device__ float g_Ae[NBHC*64];

// bf16 split buffers
__device__ __nv_bfloat16 g_xh [BT*DM];
__device__ __nv_bfloat16 g_xl [BT*DM];
__device__ __nv_bfloat16 g_f1h[BT*DFFP];
__device__ __nv_bfloat16 g_f1l[BT*DFFP];
__device__ __nv_bfloat16 g_WTh [4096*1024];    // QKVG weights transposed [4096][1024]
__device__ __nv_bfloat16 g_WTl [4096*1024];
__device__ __nv_bfloat16 g_WoTh[1024*1024];
__device__ __nv_bfloat16 g_WoTl[1024*1024];
__device__ __nv_bfloat16 g_W12Th[2*DFFP*1024]; // [5632][1024]
__device__ __nv_bfloat16 g_W12Tl[2*DFFP*1024];
__device__ __nv_bfloat16 g_W3Th[1024*DFFP];    // [1024][2816]
__device__ __nv_bfloat16 g_W3Tl[1024*DFFP];

// ---------------- PTX helpers (all sm_80-era, legal on compute_103) ----------------
__device__ __forceinline__ u32 s2u(const void* p) {
    u32 a;
    asm("{ .reg .u64 t; cvta.to.shared.u64 t, %1; cvt.u32.u64 %0, t; }" : "=r"(a) : "l"(p));
    return a;
}
__device__ __forceinline__ void ldsm_x4(u32* r, u32 addr) {
    asm volatile("ldmatrix.sync.aligned.m8n8.x4.shared.b16 {%0,%1,%2,%3}, [%4];"
        : "=r"(r[0]), "=r"(r[1]), "=r"(r[2]), "=r"(r[3]) : "r"(addr));
}
__device__ __forceinline__ void mma16816(float* c, const u32* a, const u32* b) {
    asm volatile(
        "mma.sync.aligned.m16n8k16.row.col.f32.bf16.bf16.f32 "
        "{%0,%1,%2,%3}, {%4,%5,%6,%7}, {%8,%9}, {%0,%1,%2,%3};"
        : "+f"(c[0]), "+f"(c[1]), "+f"(c[2]), "+f"(c[3])
        : "r"(a[0]), "r"(a[1]), "r"(a[2]), "r"(a[3]), "r"(b[0]), "r"(b[1]));
}
__device__ __forceinline__ void cp16(u32 dst, const void* src) {
    asm volatile("cp.async.cg.shared.global [%0], [%1], 16;" :: "r"(dst), "l"(src));
}
__device__ __forceinline__ void cp_commit() {
    asm volatile("cp.async.commit_group;" ::: "memory");
}
template<int N>
__device__ __forceinline__ void cp_wait() {
    asm volatile("cp.async.wait_group %0;" :: "n"(N) : "memory");
}

// ---------------- bf16(-split) warp-MMA GEMM, cp.async double-buffered -------------
// TERMS=3: C = Ah*Bh + Ah*Bl + Al*Bh (near-fp32 accuracy)
// TERMS=1: C = Ah*Bh (single bf16; 1/3 the MMAs, 1/2 the smem)
// 128x128 CTA tile, BK=64, 256 threads = 8 warps (2m x 4n), warp tile 64x32.
#define RSB 144                    // smem row stride bytes (128B data + 16B pad)
#define TILE_BYTES (128*RSB)       // 18432
#define GEMM_SMEM3 (2*4*TILE_BYTES)  // 147456
#define GEMM_SMEM1 (2*2*TILE_BYTES)  // 73728

template<int TERMS>
__global__ __launch_bounds__(256) void bfgemm_kernel(
    const __nv_bfloat16* __restrict__ Ah, const __nv_bfloat16* __restrict__ Al,
    const __nv_bfloat16* __restrict__ Bh, const __nv_bfloat16* __restrict__ Bl,
    float* C0, float* C1, float* C2, float* C3,
    const float* __restrict__ R,
    int K, int Nper)
{
    extern __shared__ char sm[];
    constexpr int NTILES = (TERMS == 3) ? 4 : 2;
    constexpr u32 STAGE  = (u32)NTILES * TILE_BYTES;
    constexpr u32 OFF_B  = (TERMS == 3) ? 2u*TILE_BYTES : 1u*TILE_BYTES;

    const int tid  = threadIdx.x;
    const int lane = tid & 31;
    const int wid  = tid >> 5;
    const int wr   = wid >> 2;     // 0..1  (m)
    const int wc   = wid & 3;      // 0..3  (n)
    const int bn = blockIdx.x * 128;
    const int bm = blockIdx.y * 128;

    const int lrow  = tid >> 1;    // 0..127
    const int lhalf = tid & 1;     // which 64B half of the 128B row

    float acc[4][4][4];
    #pragma unroll
    for (int i = 0; i < 4; ++i)
        #pragma unroll
        for (int j = 0; j < 4; ++j)
            #pragma unroll
            for (int q = 0; q < 4; ++q) acc[i][j][q] = 0.0f;

    const char* gAh = (const char*)(Ah + (size_t)(bm + lrow) * K) + lhalf * 64;
    const char* gAl = (TERMS == 3) ? (const char*)(Al + (size_t)(bm + lrow) * K) + lhalf * 64 : nullptr;
    const char* gBh = (const char*)(Bh + (size_t)(bn + lrow) * K) + lhalf * 64;
    const char* gBl = (TERMS == 3) ? (const char*)(Bl + (size_t)(bn + lrow) * K) + lhalf * 64 : nullptr;
    const u32 so = (u32)lrow * RSB + (u32)lhalf * 64;
    const u32 uS = s2u(sm);

    const int niter = K >> 6;

    // issue loads for stage `it` into buffer it&1
    auto issue = [&](int it) {
        const int kb = it * 128;   // byte offset into bf16 row
        const u32 ub = uS + (u32)(it & 1) * STAGE + so;
        #pragma unroll
        for (int i = 0; i < 4; ++i) {
            cp16(ub         + i*16, gAh + kb + i*16);
            cp16(ub + OFF_B + i*16, gBh + kb + i*16);
            if (TERMS == 3) {
                cp16(ub +   TILE_BYTES + i*16, gAl + kb + i*16);
                cp16(ub + 3*TILE_BYTES + i*16, gBl + kb + i*16);
            }
        }
        cp_commit();
    };

    issue(0);

    for (int it = 0; it < niter; ++it) {
        if (it + 1 < niter) { issue(it + 1); cp_wait<1>(); }
        else                { cp_wait<0>(); }
        __syncthreads();

        const u32 ubuf = uS + (u32)(it & 1) * STAGE;
        const u32 uAh = ubuf;
        const u32 uBh = ubuf + OFF_B;
        const u32 uAl = ubuf + TILE_BYTES;      // TERMS==3 only
        const u32 uBl = ubuf + 3*TILE_BYTES;    // TERMS==3 only

        #pragma unroll
        for (int ks = 0; ks < 4; ++ks) {
            const u32 coff = (u32)ks * 32 + ((u32)(lane >> 4)) * 16;
            const u32 rsel = (u32)(lane & 15);
            u32 ah[4][4], al[4][4], bh[4][2], bl[4][2];

            #pragma unroll
            for (int mi = 0; mi < 4; ++mi) {
                const u32 ra = (u32)(wr*64 + mi*16) * RSB + rsel * RSB + coff;
                ldsm_x4(ah[mi], uAh + ra);
                if (TERMS == 3) ldsm_x4(al[mi], uAl + ra);
            }
            #pragma unroll
            for (int jj = 0; jj < 2; ++jj) {
                const u32 rb = (u32)(wc*32 + jj*16) * RSB + rsel * RSB + coff;
                u32 t[4];
                ldsm_x4(t, uBh + rb);
                bh[jj*2+0][0] = t[0]; bh[jj*2+0][1] = t[2];
                bh[jj*2+1][0] = t[1]; bh[jj*2+1][1] = t[3];
                if (TERMS == 3) {
                    ldsm_x4(t, uBl + rb);
                    bl[jj*2+0][0] = t[0]; bl[jj*2+0][1] = t[2];
                    bl[jj*2+1][0] = t[1]; bl[jj*2+1][1] = t[3];
                }
            }

            #pragma unroll
            for (int mi = 0; mi < 4; ++mi)
                #pragma unroll
                for (int nj = 0; nj < 4; ++nj) {
                    mma16816(acc[mi][nj], ah[mi], bh[nj]);
                    if (TERMS == 3) {
                        mma16816(acc[mi][nj], ah[mi], bl[nj]);
                        mma16816(acc[mi][nj], al[mi], bh[nj]);
                    }
                }
        }
        __syncthreads();
    }

    // epilogue: fragment c0,c1 -> row g; c2,c3 -> row g+8; cols 2t,2t+1
    const int arr = bn / Nper;
    float* C = (arr == 0) ? C0 : (arr == 1) ? C1 : (arr == 2) ? C2 : C3;
    const int cb = bn - arr * Nper;

    #pragma unroll
    for (int mi = 0; mi < 4; ++mi) {
        const int r0 = bm + wr*64 + mi*16 + (lane >> 2);
        #pragma unroll
        for (int nj = 0; nj < 4; ++nj) {
            const int col = cb + wc*32 + nj*8 + (lane & 3)*2;
            float2 v0 = make_float2(acc[mi][nj][0], acc[mi][nj][1]);
            float2 v1 = make_float2(acc[mi][nj][2], acc[mi][nj][3]);
            if (R) {
                const float2 q0 = *(const float2*)(R + (size_t)r0 * Nper + col);
                const float2 q1 = *(const float2*)(R + (size_t)(r0+8) * Nper + col);
                v0.x += q0.x; v0.y += q0.y;
                v1.x += q1.x; v1.y += q1.y;
            }
            *(float2*)(C + (size_t)r0     * Nper + col) = v0;
            *(float2*)(C + (size_t)(r0+8) * Nper + col) = v1;
        }
    }
}

// ---------------- transpose + bf16 split: W[K,N] -> WT_hi/lo[N(+off)][Kdst] ----------
__global__ void transpose_split_kernel(const float* __restrict__ src,
                                       __nv_bfloat16* __restrict__ dh,
                                       __nv_bfloat16* __restrict__ dl,
                                       int K, int N, int Kdst, int rowOff)
{
    __shared__ float t[32][33];
    const int k0 = blockIdx.x * 32;
    const int n0 = blockIdx.y * 32;
    const int tx = threadIdx.x, ty = threadIdx.y;

    #pragma unroll
    for (int i = 0; i < 4; ++i) {
        const int kk = k0 + ty + i*8;
        const int nn = n0 + tx;
        t[ty + i*8][tx] = (kk < K && nn < N) ? src[(size_t)kk * N + nn] : 0.0f;
    }
    __syncthreads();
    #pragma unroll
    for (int i = 0; i < 4; ++i) {
        const int nn = n0 + ty + i*8;
        const int kk = k0 + tx;
        const float v = t[tx][ty + i*8];
        const __nv_bfloat16 h = __float2bfloat16(v);
        const size_t di = (size_t)(nn + rowOff) * Kdst + kk;
        dh[di] = h;
        if (dl) {
            const float res = v - __bfloat162float(h);
            dl[di] = __float2bfloat16(res);
        }
    }
}

// ---------------- RMSNorm fused with bf16 split ----------------
__global__ void rmsnorm_split_kernel(const float* __restrict__ x,
                                     const float* __restrict__ g,
                                     __nv_bfloat16* __restrict__ oh,
                                     __nv_bfloat16* __restrict__ ol)
{
    const int row = blockIdx.x;
    const float4* xr = (const float4*)(x + (size_t)row * DM);
    const float4* gr = (const float4*)g;
    float4 v = xr[threadIdx.x];
    float s = v.x*v.x + v.y*v.y + v.z*v.z + v.w*v.w;
    #pragma unroll
    for (int o = 16; o > 0; o >>= 1) s += __shfl_xor_sync(0xFFFFFFFFu, s, o);
    __shared__ float red[8];
    if ((threadIdx.x & 31) == 0) red[threadIdx.x >> 5] = s;
    __syncthreads();
    float tot = red[0]+red[1]+red[2]+red[3]+red[4]+red[5]+red[6]+red[7];
    float sc = rsqrtf(tot * (1.0f/(float)DM) + 1e-6f);
    float4 gv = gr[threadIdx.x];
    float hv[4];
    hv[0] = v.x * sc * gv.x;
    hv[1] = v.y * sc * gv.y;
    hv[2] = v.z * sc * gv.z;
    hv[3] = v.w * sc * gv.w;
    const size_t base = (size_t)row * DM + threadIdx.x * 4;
    #pragma unroll
    for (int j = 0; j < 4; ++j) {
        const __nv_bfloat16 h = __float2bfloat16(hv[j]);
        oh[base + j] = h;
        if (ol) ol[base + j] = __float2bfloat16(hv[j] - __bfloat162float(h));
    }
}

// ---------------- q/k L2-norm per head + LOG-SIGMOID(gate), in place ----------------
__global__ void qknorm_kernel(float* __restrict__ q,
                              float* __restrict__ k,
                              float* __restrict__ a)
{
    const int row  = blockIdx.x;
    const int lane = threadIdx.x & 31;
    const int w    = threadIdx.x >> 5;
    float2* qr = (float2*)(q + (size_t)row * DM);
    float2* kr = (float2*)(k + (size_t)row * DM);

    #pragma unroll
    for (int it = 0; it < 2; ++it) {
        const int h = w + it * 8;
        {
            float2 v = qr[h*32 + lane];
            float s = v.x*v.x + v.y*v.y;
            #pragma unroll
            for (int o = 16; o > 0; o >>= 1) s += __shfl_xor_sync(0xFFFFFFFFu, s, o);
            float inv = 1.0f / fmaxf(sqrtf(s), 1e-12f);
            v.x *= inv; v.y *= inv;
            qr[h*32 + lane] = v;
        }
        {
            float2 v = kr[h*32 + lane];
            float s = v.x*v.x + v.y*v.y;
            #pragma unroll
            for (int o = 16; o > 0; o >>= 1) s += __shfl_xor_sync(0xFFFFFFFFu, s, o);
            float inv = 1.0f / fmaxf(sqrtf(s), 1e-12f);
            v.x *= inv; v.y *= inv;
            kr[h*32 + lane] = v;
        }
    }
    float* ar = a + (size_t)row * DM;
    for (int i = threadIdx.x; i < DM; i += 256) {
        float z = ar[i];
        ar[i] = (z >= 0.0f) ? -log1pf(__expf(-z)) : (z - log1pf(__expf(z)));
    }
}

// ---------------- chunked GLA kernels ----------------
__global__ __launch_bounds__(256) void chunk_summary_kernel(
    float* __restrict__ q, float* __restrict__ k,
    const float* __restrict__ v, const float* __restrict__ la,
    float* __restrict__ P, float* __restrict__ Ae)
{
    __shared__ float Ash[CS][64];
    __shared__ float Ks [CS][64];
    __shared__ float Vs [CS][64];

    const int bhc = blockIdx.x;
    const int bh  = bhc >> 4, c = bhc & 15;
    const int b   = bh >> 4,  h = bh & 15;
    const int tid = threadIdx.x;
    const int d   = tid & 63, j0 = tid >> 6;
    const size_t base = ((size_t)(b*1024 + c*CS)) * DM + h*64;

    #pragma unroll
    for (int i = 0; i < 16; ++i) {
        const int j = j0 + 4*i;
        Ash[j][d] = la[base + (size_t)j*DM + d];
    }
    __syncthreads();

    if (tid < 64) {
        float cum = 0.0f, Aj = 1.0f;
        #pragma unroll
        for (int j = 0; j < CS; ++j) {
            cum += Ash[j][tid];
            Aj = __expf(cum);
            Ash[j][tid] = Aj;
        }
        Ae[(size_t)bhc*64 + tid] = Aj;
    }
    __syncthreads();

    #pragma unroll
    for (int i = 0; i < 16; ++i) {
        const int j = j0 + 4*i;
        const size_t off = base + (size_t)j*DM + d;
        const float A = Ash[j][d];
        q[off] = q[off] * A;
        const float kv = __fdividef(k[off], A);
        k[off] = kv;
        Ks[j][d] = kv;
        Vs[j][d] = v[off];
    }
    __syncthreads();

    const int dr = (tid >> 4) << 2;
    const int ec = (tid & 15) << 2;
    float acc[4][4];
    #pragma unroll
    for (int i = 0; i < 4; ++i)
        #pragma unroll
        for (int j = 0; j < 4; ++j) acc[i][j] = 0.0f;

    #pragma unroll 4
    for (int i2 = 0; i2 < CS; ++i2) {
        float kk[4], vv[4];
        *(float4*)kk = *(const float4*)&Ks[i2][dr];
        *(float4*)vv = *(const float4*)&Vs[i2][ec];
        #pragma unroll
        for (int i = 0; i < 4; ++i)
            #pragma unroll
            for (int j = 0; j < 4; ++j)
                acc[i][j] = fmaf(kk[i], vv[j], acc[i][j]);
    }

    float* Pp = P + (size_t)bhc * 4096;
    #pragma unroll
    for (int ii = 0; ii < 4; ++ii) {
        const float aend = Ash[CS-1][dr+ii];
        float4 o4;
        o4.x = acc[ii][0]*aend; o4.y = acc[ii][1]*aend;
        o4.z = acc[ii][2]*aend; o4.w = acc[ii][3]*aend;
        *(float4*)&Pp[(dr+ii)*64 + ec] = o4;
    }
}

__global__ __launch_bounds__(256) void chunk_state_kernel(
    const float* __restrict__ P, const float* __restrict__ Ae,
    float* __restrict__ S)
{
    const int bh  = blockIdx.x;
    const int tid = threadIdx.x;
    const int e   = tid & 63;
    const int d0  = tid >> 6;
    __shared__ float sae[64];

    float s[16];
    #pragma unroll
    for (int i = 0; i < 16; ++i) s[i] = 0.0f;

    for (int c = 0; c < NC; ++c) {
        const size_t idx = (size_t)bh*NC + c;
        if (tid < 64) sae[tid] = Ae[idx*64 + tid];
        __syncthreads();
        const float* Pc = P + idx*4096;
        float*       Sc = S + idx*4096;
        #pragma unroll
        for (int i = 0; i < 16; ++i) {
            const int d = d0 + 4*i;
            Sc[d*64 + e] = s[i];
            s[i] = fmaf(sae[d], s[i], Pc[d*64 + e]);
        }
        __syncthreads();
    }
}

__global__ __launch_bounds__(256) void chunk_output_kernel(
    const float* __restrict__ q, const float* __restrict__ k,
    const float* __restrict__ v, const float* __restrict__ S,
    __nv_bfloat16* __restrict__ oh, __nv_bfloat16* __restrict__ ol)
{
    extern __shared__ float sm3[];
    float (*Qs)[PAD] = (float(*)[PAD])(sm3);
    float (*KT)[PAD] = (float(*)[PAD])(sm3 + 64*PAD);
    float (*Bs)[PAD] = (float(*)[PAD])(sm3 + 2*64*PAD);
    float (*Sc)[PAD] = (float(*)[PAD])(sm3 + 3*64*PAD);

    const int bhc = blockIdx.x;
    const int bh  = bhc >> 4, c = bhc & 15;
    const int b   = bh >> 4,  h = bh & 15;
    const int tid = threadIdx.x;
    const int d   = tid & 63, j0 = tid >> 6;
    const size_t base = ((size_t)(b*1024 + c*CS)) * DM + h*64;
    const float* Sb = S + (size_t)bhc * 4096;

    #pragma unroll
    for (int i = 0; i < 16; ++i) {
        const int j = j0 + 4*i;
        Qs[j][d] = q[base + (size_t)j*DM + d];
        KT[d][j] = k[base + (size_t)j*DM + d];
        Bs[j][d] = Sb[j*64 + d];
    }
    __syncthreads();

    const int tr = (tid >> 4) << 2;
    const int tc = (tid & 15) << 2;

    float acc[4][4], sca[4][4];
    #pragma unroll
    for (int i = 0; i < 4; ++i)
        #pragma unroll
        for (int j = 0; j < 4; ++j) { acc[i][j] = 0.0f; sca[i][j] = 0.0f; }

    #pragma unroll 4
    for (int dd = 0; dd < 64; ++dd) {
        float bv[4], kv[4], av[4];
        *(float4*)bv = *(const float4*)&Bs[dd][tc];
        *(float4*)kv = *(const float4*)&KT[dd][tc];
        #pragma unroll
        for (int i = 0; i < 4; ++i) av[i] = Qs[tr+i][dd];
        #pragma unroll
        for (int i = 0; i < 4; ++i)
            #pragma unroll
            for (int j = 0; j < 4; ++j) {
                acc[i][j] = fmaf(av[i], bv[j], acc[i][j]);
                sca[i][j] = fmaf(av[i], kv[j], sca[i][j]);
            }
    }

    #pragma unroll
    for (int i = 0; i < 4; ++i)
        #pragma unroll
        for (int j = 0; j < 4; ++j)
            Sc[tr+i][tc+j] = ((tc+j) <= (tr+i)) ? sca[i][j] : 0.0f;
    __syncthreads();

    #pragma unroll
    for (int i = 0; i < 16; ++i) {
        const int j = j0 + 4*i;
        Bs[j][d] = v[base + (size_t)j*DM + d];
    }
    __syncthreads();

    #pragma unroll 4
    for (int dd = 0; dd < 64; ++dd) {
        float bv[4], av[4];
        *(float4*)bv = *(const float4*)&Bs[dd][tc];
        #pragma unroll
        for (int i = 0; i < 4; ++i) av[i] = Sc[tr+i][dd];
        #pragma unroll
        for (int i = 0; i < 4; ++i)
            #pragma unroll
            for (int j = 0; j < 4; ++j)
                acc[i][j] = fmaf(av[i], bv[j], acc[i][j]);
    }

    #pragma unroll
    for (int i = 0; i < 4; ++i) {
        const size_t off = base + (size_t)(tr+i)*DM + tc;
        #pragma unroll
        for (int j = 0; j < 4; ++j) {
            const float vvo = acc[i][j];
            oh[off + j] = __float2bfloat16(vvo);
        }
    }
    (void)ol;
}

// ---------------- SwiGLU fused with bf16 (single) ----------------
__global__ void swiglu_split_kernel(const float* __restrict__ f1,
                                    const float* __restrict__ f2,
                                    __nv_bfloat16* __restrict__ gh,
                                    __nv_bfloat16* __restrict__ gl,
                                    int n4)
{
    int i = blockIdx.x * blockDim.x + threadIdx.x;
    if (i < n4) {
        float4 a = ((const float4*)f1)[i];
        float4 b = ((const float4*)f2)[i];
        float r[4];
        r[0] = a.x / (1.0f + __expf(-a.x)) * b.x;
        r[1] = a.y / (1.0f + __expf(-a.y)) * b.y;
        r[2] = a.z / (1.0f + __expf(-a.z)) * b.z;
        r[3] = a.w / (1.0f + __expf(-a.w)) * b.w;
        #pragma unroll
        for (int j = 0; j < 4; ++j)
            gh[i*4 + j] = __float2bfloat16(r[j]);
        (void)gl;
    }
}

// ---------------- host launcher ----------------
extern "C" void kernel_launch(void* const* d_in, const int* in_sizes, int n_in,
                              void* d_out, int out_size)
{
    const float* x   = (const float*)d_in[0];
    const float* Wq  = (const float*)d_in[1];
    const float* Wk  = (const float*)d_in[2];
    const float* Wv  = (const float*)d_in[3];
    const float* Wg  = (const float*)d_in[4];
    const float* Wo  = (const float*)d_in[5];
    const float* w1  = (const float*)d_in[6];
    const float* w2  = (const float*)d_in[7];
    const float* w3  = (const float*)d_in[8];
    const float* gat = (const float*)d_in[9];
    const float* gff = (const float*)d_in[10];
    float* out = (float*)d_out;

    float *pq, *pk, *pv, *pa, *px1, *pf1, *pf2, *pP, *pSs, *pAe;
    __nv_bfloat16 *pxh, *pxl, *pf1h;
    __nv_bfloat16 *pWTh, *pWTl, *pWoTh, *pW12Th, *pW3Th;
    cudaGetSymbolAddress((void**)&pq,  g_q);
    cudaGetSymbolAddress((void**)&pk,  g_k);
    cudaGetSymbolAddress((void**)&pv,  g_v);
    cudaGetSymbolAddress((void**)&pa,  g_a);
    cudaGetSymbolAddress((void**)&px1, g_x1);
    cudaGetSymbolAddress((void**)&pf1, g_f1);
    cudaGetSymbolAddress((void**)&pf2, g_f2);
    cudaGetSymbolAddress((void**)&pP,  g_P);
    cudaGetSymbolAddress((void**)&pSs, g_Ss);
    cudaGetSymbolAddress((void**)&pAe, g_Ae);
    cudaGetSymbolAddress((void**)&pxh, g_xh);
    cudaGetSymbolAddress((void**)&pxl, g_xl);
    cudaGetSymbolAddress((void**)&pf1h, g_f1h);
    cudaGetSymbolAddress((void**)&pWTh, g_WTh);
    cudaGetSymbolAddress((void**)&pWTl, g_WTl);
    cudaGetSymbolAddress((void**)&pWoTh, g_WoTh);
    cudaGetSymbolAddress((void**)&pW12Th, g_W12Th);
    cudaGetSymbolAddress((void**)&pW3Th, g_W3Th);

    static bool attr_done = false;
    if (!attr_done) {
        cudaFuncSetAttribute(chunk_output_kernel,
                             cudaFuncAttributeMaxDynamicSharedMemorySize,
                             4 * 64 * PAD * (int)sizeof(float));
        cudaFuncSetAttribute(bfgemm_kernel<3>,
                             cudaFuncAttributeMaxDynamicSharedMemorySize,
                             GEMM_SMEM3);
        cudaFuncSetAttribute(bfgemm_kernel<1>,
                             cudaFuncAttributeMaxDynamicSharedMemorySize,
                             GEMM_SMEM1);
        attr_done = true;
    }

    dim3 tb(32, 8);
    // 0) transpose + split weights (hi/lo for QKVG; hi only for single-term GEMMs)
    transpose_split_kernel<<<dim3(32, 32), tb>>>(Wq, pWTh, pWTl, 1024, 1024, 1024, 0);
    transpose_split_kernel<<<dim3(32, 32), tb>>>(Wk, pWTh, pWTl, 1024, 1024, 1024, 1024);
    transpose_split_kernel<<<dim3(32, 32), tb>>>(Wv, pWTh, pWTl, 1024, 1024, 1024, 2048);
    transpose_split_kernel<<<dim3(32, 32), tb>>>(Wg, pWTh, pWTl, 1024, 1024, 1024, 3072);
    transpose_split_kernel<<<dim3(32, 32), tb>>>(Wo, pWoTh, nullptr, 1024, 1024, 1024, 0);
    transpose_split_kernel<<<dim3(32, DFFP/32), tb>>>(w1, pW12Th, nullptr, 1024, DFF, 1024, 0);
    transpose_split_kernel<<<dim3(32, DFFP/32), tb>>>(w2, pW12Th, nullptr, 1024, DFF, 1024, DFFP);
    transpose_split_kernel<<<dim3(DFFP/32, 32), tb>>>(w3, pW3Th, nullptr, DFF, 1024, DFFP, 0);

    // 1) h = rmsnorm(x, g_attn), split to bf16 hi/lo (feeds 3-term QKVG)
    rmsnorm_split_kernel<<<BT, 256>>>(x, gat, pxh, pxl);

    // 2) q,k,v,gate = h @ {Wq,Wk,Wv,Wg}  (3-term: accuracy-critical gate path)
    bfgemm_kernel<3><<<dim3(4096/128, BT/128), 256, GEMM_SMEM3>>>(
        pxh, pxl, pWTh, pWTl, pq, pk, pv, pa, nullptr, 1024, 1024);

    // 3) l2norm(q), l2norm(k), log-sigmoid(gate)
    qknorm_kernel<<<BT, 256>>>(pq, pk, pa);

    // 4) chunked GLA -> o (bf16 hi only)
    chunk_summary_kernel<<<NBHC, 256>>>(pq, pk, pv, pa, pP, pAe);
    chunk_state_kernel  <<<32,   256>>>(pP, pAe, pSs);
    chunk_output_kernel <<<NBHC, 256, 4*64*PAD*(int)sizeof(float)>>>(pq, pk, pv, pSs, pxh, nullptr);

    // 5) x1 = x + o @ Wo   (single bf16)
    bfgemm_kernel<1><<<dim3(1024/128, BT/128), 256, GEMM_SMEM1>>>(
        pxh, nullptr, pWoTh, nullptr, px1, nullptr, nullptr, nullptr, x, 1024, 1024);

    // 6) h = rmsnorm(x1, g_ffn), bf16 hi only
    rmsnorm_split_kernel<<<BT, 256>>>(px1, gff, pxh, nullptr);

    // 7) f1 = h @ w1 ; f2 = h @ w2   (single bf16, one N=5632 GEMM)
    bfgemm_kernel<1><<<dim3(2*DFFP/128, BT/128), 256, GEMM_SMEM1>>>(
        pxh, nullptr, pW12Th, nullptr, pf1, pf2, nullptr, nullptr, nullptr, 1024, DFFP);

    // 8) gated = silu(f1) * f2, bf16
    {
        const int n4 = BT * DFFP / 4;
        swiglu_split_kernel<<<(n4 + 255)/256, 256>>>(pf1, pf2, pf1h, nullptr, n4);
    }

    // 9) out = x1 + gated @ w3  (single bf16, K = 2816 padded)
    bfgemm_kernel<1><<<dim3(1024/128, BT/128), 256, GEMM_SMEM1>>>(
        pf1h, nullptr, pW3Th, nullptr, out, nullptr, nullptr, nullptr, px1, DFFP, 1024);
}

// round 13
// speedup vs baseline: 4.7506x; 1.3388x over previous
#include <cuda_runtime.h>
#include <cuda_bf16.h>
#include <math.h>

#define BT   2048     // B*T
#define DM   1024     // d_model
#define NH   16
#define DKV  64
#define DFF  2736
#define DFFP 2816     // DFF padded to multiple of 128
#define NC   16       // chunks per sequence
#define CS   64       // chunk size
#define NBHC 512      // B*H*NC
#define PAD  68       // smem row stride (floats) for chunk_output

typedef unsigned long long u64;
typedef unsigned int u32;

// ---------------- scratch (static device globals; no allocation) ----------------
__device__ float g_q [BT*DM];
__device__ float g_k [BT*DM];
__device__ float g_v [BT*DM];
__device__ float g_a [BT*DM];
__device__ float g_x1[BT*DM];
__device__ float g_f1[BT*DFFP];
__device__ float g_f2[BT*DFFP];
__device__ float g_P [NBHC*4096];
__device__ float g_Ss[NBHC*4096];
__device__ float g_Ae[NBHC*64];

// bf16 buffers
__device__ __nv_bfloat16 g_xh [BT*DM];
__device__ __nv_bfloat16 g_f1h[BT*DFFP];
__device__ __nv_bfloat16 g_WTh [4096*1024];    // QKVG weights transposed [4096][1024]
__device__ __nv_bfloat16 g_WoTh[1024*1024];
__device__ __nv_bfloat16 g_W12Th[2*DFFP*1024]; // [5632][1024]
__device__ __nv_bfloat16 g_W3Th[1024*DFFP];    // [1024][2816]

// ---------------- PTX helpers (all sm_80-era, legal on compute_103) ----------------
__device__ __forceinline__ u32 s2u(const void* p) {
    u32 a;
    asm("{ .reg .u64 t; cvta.to.shared.u64 t, %1; cvt.u32.u64 %0, t; }" : "=r"(a) : "l"(p));
    return a;
}
__device__ __forceinline__ void ldsm_x4(u32* r, u32 addr) {
    asm volatile("ldmatrix.sync.aligned.m8n8.x4.shared.b16 {%0,%1,%2,%3}, [%4];"
        : "=r"(r[0]), "=r"(r[1]), "=r"(r[2]), "=r"(r[3]) : "r"(addr));
}
__device__ __forceinline__ void mma16816(float* c, const u32* a, const u32* b) {
    asm volatile(
        "mma.sync.aligned.m16n8k16.row.col.f32.bf16.bf16.f32 "
        "{%0,%1,%2,%3}, {%4,%5,%6,%7}, {%8,%9}, {%0,%1,%2,%3};"
        : "+f"(c[0]), "+f"(c[1]), "+f"(c[2]), "+f"(c[3])
        : "r"(a[0]), "r"(a[1]), "r"(a[2]), "r"(a[3]), "r"(b[0]), "r"(b[1]));
}
__device__ __forceinline__ void cp16(u32 dst, const void* src) {
    asm volatile("cp.async.cg.shared.global [%0], [%1], 16;" :: "r"(dst), "l"(src));
}
__device__ __forceinline__ void cp_commit() {
    asm volatile("cp.async.commit_group;" ::: "memory");
}
template<int N>
__device__ __forceinline__ void cp_wait() {
    asm volatile("cp.async.wait_group %0;" :: "n"(N) : "memory");
}

// ---------------- bf16(-split) warp-MMA GEMM, cp.async double-buffered -------------
// TERMS=3: C = Ah*Bh + Ah*Bl + Al*Bh (near-fp32)   TERMS=1: C = Ah*Bh
// 128x128 CTA tile, BK=64, 256 threads = 8 warps (2m x 4n), warp tile 64x32.
#define RSB 144                    // smem row stride bytes (128B data + 16B pad)
#define TILE_BYTES (128*RSB)       // 18432
#define GEMM_SMEM3 (2*4*TILE_BYTES)  // 147456
#define GEMM_SMEM1 (2*2*TILE_BYTES)  // 73728

template<int TERMS>
__global__ __launch_bounds__(256) void bfgemm_kernel(
    const __nv_bfloat16* __restrict__ Ah, const __nv_bfloat16* __restrict__ Al,
    const __nv_bfloat16* __restrict__ Bh, const __nv_bfloat16* __restrict__ Bl,
    float* C0, float* C1, float* C2, float* C3,
    const float* __restrict__ R,
    int K, int Nper)
{
    extern __shared__ char sm[];
    constexpr int NTILES = (TERMS == 3) ? 4 : 2;
    constexpr u32 STAGE  = (u32)NTILES * TILE_BYTES;
    constexpr u32 OFF_B  = (TERMS == 3) ? 2u*TILE_BYTES : 1u*TILE_BYTES;

    const int tid  = threadIdx.x;
    const int lane = tid & 31;
    const int wid  = tid >> 5;
    const int wr   = wid >> 2;     // 0..1  (m)
    const int wc   = wid & 3;      // 0..3  (n)
    const int bn = blockIdx.x * 128;
    const int bm = blockIdx.y * 128;

    const int lrow  = tid >> 1;    // 0..127
    const int lhalf = tid & 1;     // which 64B half of the 128B row

    float acc[4][4][4];
    #pragma unroll
    for (int i = 0; i < 4; ++i)
        #pragma unroll
        for (int j = 0; j < 4; ++j)
            #pragma unroll
            for (int q = 0; q < 4; ++q) acc[i][j][q] = 0.0f;

    const char* gAh = (const char*)(Ah + (size_t)(bm + lrow) * K) + lhalf * 64;
    const char* gAl = (TERMS == 3) ? (const char*)(Al + (size_t)(bm + lrow) * K) + lhalf * 64 : nullptr;
    const char* gBh = (const char*)(Bh + (size_t)(bn + lrow) * K) + lhalf * 64;
    const char* gBl = (TERMS == 3) ? (const char*)(Bl + (size_t)(bn + lrow) * K) + lhalf * 64 : nullptr;
    const u32 so = (u32)lrow * RSB + (u32)lhalf * 64;
    const u32 uS = s2u(sm);

    const int niter = K >> 6;

    // issue loads for stage `it` into buffer it&1
    auto issue = [&](int it) {
        const int kb = it * 128;   // byte offset into bf16 row
        const u32 ub = uS + (u32)(it & 1) * STAGE + so;
        #pragma unroll
        for (int i = 0; i < 4; ++i) {
            cp16(ub         + i*16, gAh + kb + i*16);
            cp16(ub + OFF_B + i*16, gBh + kb + i*16);
            if (TERMS == 3) {
                cp16(ub +   TILE_BYTES + i*16, gAl + kb + i*16);
                cp16(ub + 3*TILE_BYTES + i*16, gBl + kb + i*16);
            }
        }
        cp_commit();
    };

    issue(0);

    for (int it = 0; it < niter; ++it) {
        if (it + 1 < niter) { issue(it + 1); cp_wait<1>(); }
        else                { cp_wait<0>(); }
        __syncthreads();

        const u32 ubuf = uS + (u32)(it & 1) * STAGE;
        const u32 uAh = ubuf;
        const u32 uBh = ubuf + OFF_B;
        const u32 uAl = ubuf + TILE_BYTES;      // TERMS==3 only
        const u32 uBl = ubuf + 3*TILE_BYTES;    // TERMS==3 only

        #pragma unroll
        for (int ks = 0; ks < 4; ++ks) {
            const u32 coff = (u32)ks * 32 + ((u32)(lane >> 4)) * 16;
            const u32 rsel = (u32)(lane & 15);
            u32 ah[4][4], al[4][4], bh[4][2], bl[4][2];

            #pragma unroll
            for (int mi = 0; mi < 4; ++mi) {
                const u32 ra = (u32)(wr*64 + mi*16) * RSB + rsel * RSB + coff;
                ldsm_x4(ah[mi], uAh + ra);
                if (TERMS == 3) ldsm_x4(al[mi], uAl + ra);
            }
            #pragma unroll
            for (int jj = 0; jj < 2; ++jj) {
                const u32 rb = (u32)(wc*32 + jj*16) * RSB + rsel * RSB + coff;
                u32 t[4];
                ldsm_x4(t, uBh + rb);
                bh[jj*2+0][0] = t[0]; bh[jj*2+0][1] = t[2];
                bh[jj*2+1][0] = t[1]; bh[jj*2+1][1] = t[3];
                if (TERMS == 3) {
                    ldsm_x4(t, uBl + rb);
                    bl[jj*2+0][0] = t[0]; bl[jj*2+0][1] = t[2];
                    bl[jj*2+1][0] = t[1]; bl[jj*2+1][1] = t[3];
                }
            }

            #pragma unroll
            for (int mi = 0; mi < 4; ++mi)
                #pragma unroll
                for (int nj = 0; nj < 4; ++nj) {
                    mma16816(acc[mi][nj], ah[mi], bh[nj]);
                    if (TERMS == 3) {
                        mma16816(acc[mi][nj], ah[mi], bl[nj]);
                        mma16816(acc[mi][nj], al[mi], bh[nj]);
                    }
                }
        }
        __syncthreads();
    }

    // epilogue: fragment c0,c1 -> row g; c2,c3 -> row g+8; cols 2t,2t+1
    const int arr = bn / Nper;
    float* C = (arr == 0) ? C0 : (arr == 1) ? C1 : (arr == 2) ? C2 : C3;
    const int cb = bn - arr * Nper;

    #pragma unroll
    for (int mi = 0; mi < 4; ++mi) {
        const int r0 = bm + wr*64 + mi*16 + (lane >> 2);
        #pragma unroll
        for (int nj = 0; nj < 4; ++nj) {
            const int col = cb + wc*32 + nj*8 + (lane & 3)*2;
            float2 v0 = make_float2(acc[mi][nj][0], acc[mi][nj][1]);
            float2 v1 = make_float2(acc[mi][nj][2], acc[mi][nj][3]);
            if (R) {
                const float2 q0 = *(const float2*)(R + (size_t)r0 * Nper + col);
                const float2 q1 = *(const float2*)(R + (size_t)(r0+8) * Nper + col);
                v0.x += q0.x; v0.y += q0.y;
                v1.x += q1.x; v1.y += q1.y;
            }
            *(float2*)(C + (size_t)r0     * Nper + col) = v0;
            *(float2*)(C + (size_t)(r0+8) * Nper + col) = v1;
        }
    }
}

// ---------------- transpose + bf16: W[K,N] -> WT[N(+off)][Kdst] ----------
__global__ void transpose_split_kernel(const float* __restrict__ src,
                                       __nv_bfloat16* __restrict__ dh,
                                       __nv_bfloat16* __restrict__ dl,
                                       int K, int N, int Kdst, int rowOff)
{
    __shared__ float t[32][33];
    const int k0 = blockIdx.x * 32;
    const int n0 = blockIdx.y * 32;
    const int tx = threadIdx.x, ty = threadIdx.y;

    #pragma unroll
    for (int i = 0; i < 4; ++i) {
        const int kk = k0 + ty + i*8;
        const int nn = n0 + tx;
        t[ty + i*8][tx] = (kk < K && nn < N) ? src[(size_t)kk * N + nn] : 0.0f;
    }
    __syncthreads();
    #pragma unroll
    for (int i = 0; i < 4; ++i) {
        const int nn = n0 + ty + i*8;
        const int kk = k0 + tx;
        const float v = t[tx][ty + i*8];
        const __nv_bfloat16 h = __float2bfloat16(v);
        const size_t di = (size_t)(nn + rowOff) * Kdst + kk;
        dh[di] = h;
        if (dl) {
            const float res = v - __bfloat162float(h);
            dl[di] = __float2bfloat16(res);
        }
    }
}

// ---------------- RMSNorm fused with bf16 convert ----------------
__global__ void rmsnorm_split_kernel(const float* __restrict__ x,
                                     const float* __restrict__ g,
                                     __nv_bfloat16* __restrict__ oh,
                                     __nv_bfloat16* __restrict__ ol)
{
    const int row = blockIdx.x;
    const float4* xr = (const float4*)(x + (size_t)row * DM);
    const float4* gr = (const float4*)g;
    float4 v = xr[threadIdx.x];
    float s = v.x*v.x + v.y*v.y + v.z*v.z + v.w*v.w;
    #pragma unroll
    for (int o = 16; o > 0; o >>= 1) s += __shfl_xor_sync(0xFFFFFFFFu, s, o);
    __shared__ float red[8];
    if ((threadIdx.x & 31) == 0) red[threadIdx.x >> 5] = s;
    __syncthreads();
    float tot = red[0]+red[1]+red[2]+red[3]+red[4]+red[5]+red[6]+red[7];
    float sc = rsqrtf(tot * (1.0f/(float)DM) + 1e-6f);
    float4 gv = gr[threadIdx.x];
    float hv[4];
    hv[0] = v.x * sc * gv.x;
    hv[1] = v.y * sc * gv.y;
    hv[2] = v.z * sc * gv.z;
    hv[3] = v.w * sc * gv.w;
    const size_t base = (size_t)row * DM + threadIdx.x * 4;
    #pragma unroll
    for (int j = 0; j < 4; ++j) {
        const __nv_bfloat16 h = __float2bfloat16(hv[j]);
        oh[base + j] = h;
        if (ol) ol[base + j] = __float2bfloat16(hv[j] - __bfloat162float(h));
    }
}

// ---------------- q/k L2-norm per head + LOG-SIGMOID(gate), in place ----------------
__global__ void qknorm_kernel(float* __restrict__ q,
                              float* __restrict__ k,
                              float* __restrict__ a)
{
    const int row  = blockIdx.x;
    const int lane = threadIdx.x & 31;
    const int w    = threadIdx.x >> 5;
    float2* qr = (float2*)(q + (size_t)row * DM);
    float2* kr = (float2*)(k + (size_t)row * DM);

    #pragma unroll
    for (int it = 0; it < 2; ++it) {
        const int h = w + it * 8;
        {
            float2 v = qr[h*32 + lane];
            float s = v.x*v.x + v.y*v.y;
            #pragma unroll
            for (int o = 16; o > 0; o >>= 1) s += __shfl_xor_sync(0xFFFFFFFFu, s, o);
            float inv = 1.0f / fmaxf(sqrtf(s), 1e-12f);
            v.x *= inv; v.y *= inv;
            qr[h*32 + lane] = v;
        }
        {
            float2 v = kr[h*32 + lane];
            float s = v.x*v.x + v.y*v.y;
            #pragma unroll
            for (int o = 16; o > 0; o >>= 1) s += __shfl_xor_sync(0xFFFFFFFFu, s, o);
            float inv = 1.0f / fmaxf(sqrtf(s), 1e-12f);
            v.x *= inv; v.y *= inv;
            kr[h*32 + lane] = v;
        }
    }
    float* ar = a + (size_t)row * DM;
    for (int i = threadIdx.x; i < DM; i += 256) {
        float z = ar[i];
        ar[i] = (z >= 0.0f) ? -log1pf(__expf(-z)) : (z - log1pf(__expf(z)));
    }
}

// ---------------- chunked GLA kernels ----------------
__global__ __launch_bounds__(256) void chunk_summary_kernel(
    float* __restrict__ q, float* __restrict__ k,
    const float* __restrict__ v, const float* __restrict__ la,
    float* __restrict__ P, float* __restrict__ Ae)
{
    __shared__ float Ash[CS][64];
    __shared__ float Ks [CS][64];
    __shared__ float Vs [CS][64];

    const int bhc = blockIdx.x;
    const int bh  = bhc >> 4, c = bhc & 15;
    const int b   = bh >> 4,  h = bh & 15;
    const int tid = threadIdx.x;
    const int d   = tid & 63, j0 = tid >> 6;
    const size_t base = ((size_t)(b*1024 + c*CS)) * DM + h*64;

    #pragma unroll
    for (int i = 0; i < 16; ++i) {
        const int j = j0 + 4*i;
        Ash[j][d] = la[base + (size_t)j*DM + d];
    }
    __syncthreads();

    if (tid < 64) {
        float cum = 0.0f, Aj = 1.0f;
        #pragma unroll
        for (int j = 0; j < CS; ++j) {
            cum += Ash[j][tid];
            Aj = __expf(cum);
            Ash[j][tid] = Aj;
        }
        Ae[(size_t)bhc*64 + tid] = Aj;
    }
    __syncthreads();

    #pragma unroll
    for (int i = 0; i < 16; ++i) {
        const int j = j0 + 4*i;
        const size_t off = base + (size_t)j*DM + d;
        const float A = Ash[j][d];
        q[off] = q[off] * A;
        const float kv = __fdividef(k[off], A);
        k[off] = kv;
        Ks[j][d] = kv;
        Vs[j][d] = v[off];
    }
    __syncthreads();

    const int dr = (tid >> 4) << 2;
    const int ec = (tid & 15) << 2;
    float acc[4][4];
    #pragma unroll
    for (int i = 0; i < 4; ++i)
        #pragma unroll
        for (int j = 0; j < 4; ++j) acc[i][j] = 0.0f;

    #pragma unroll 4
    for (int i2 = 0; i2 < CS; ++i2) {
        float kk[4], vv[4];
        *(float4*)kk = *(const float4*)&Ks[i2][dr];
        *(float4*)vv = *(const float4*)&Vs[i2][ec];
        #pragma unroll
        for (int i = 0; i < 4; ++i)
            #pragma unroll
            for (int j = 0; j < 4; ++j)
                acc[i][j] = fmaf(kk[i], vv[j], acc[i][j]);
    }

    float* Pp = P + (size_t)bhc * 4096;
    #pragma unroll
    for (int ii = 0; ii < 4; ++ii) {
        const float aend = Ash[CS-1][dr+ii];
        float4 o4;
        o4.x = acc[ii][0]*aend; o4.y = acc[ii][1]*aend;
        o4.z = acc[ii][2]*aend; o4.w = acc[ii][3]*aend;
        *(float4*)&Pp[(dr+ii)*64 + ec] = o4;
    }
}

__global__ __launch_bounds__(256) void chunk_state_kernel(
    const float* __restrict__ P, const float* __restrict__ Ae,
    float* __restrict__ S)
{
    const int bh  = blockIdx.x;
    const int tid = threadIdx.x;
    const int e   = tid & 63;
    const int d0  = tid >> 6;
    __shared__ float sae[64];

    float s[16];
    #pragma unroll
    for (int i = 0; i < 16; ++i) s[i] = 0.0f;

    for (int c = 0; c < NC; ++c) {
        const size_t idx = (size_t)bh*NC + c;
        if (tid < 64) sae[tid] = Ae[idx*64 + tid];
        __syncthreads();
        const float* Pc = P + idx*4096;
        float*       Sc = S + idx*4096;
        #pragma unroll
        for (int i = 0; i < 16; ++i) {
            const int d = d0 + 4*i;
            Sc[d*64 + e] = s[i];
            s[i] = fmaf(sae[d], s[i], Pc[d*64 + e]);
        }
        __syncthreads();
    }
}

__global__ __launch_bounds__(256) void chunk_output_kernel(
    const float* __restrict__ q, const float* __restrict__ k,
    const float* __restrict__ v, const float* __restrict__ S,
    __nv_bfloat16* __restrict__ oh)
{
    extern __shared__ float sm3[];
    float (*Qs)[PAD] = (float(*)[PAD])(sm3);
    float (*KT)[PAD] = (float(*)[PAD])(sm3 + 64*PAD);
    float (*Bs)[PAD] = (float(*)[PAD])(sm3 + 2*64*PAD);
    float (*Sc)[PAD] = (float(*)[PAD])(sm3 + 3*64*PAD);

    const int bhc = blockIdx.x;
    const int bh  = bhc >> 4, c = bhc & 15;
    const int b   = bh >> 4,  h = bh & 15;
    const int tid = threadIdx.x;
    const int d   = tid & 63, j0 = tid >> 6;
    const size_t base = ((size_t)(b*1024 + c*CS)) * DM + h*64;
    const float* Sb = S + (size_t)bhc * 4096;

    #pragma unroll
    for (int i = 0; i < 16; ++i) {
        const int j = j0 + 4*i;
        Qs[j][d] = q[base + (size_t)j*DM + d];
        KT[d][j] = k[base + (size_t)j*DM + d];
        Bs[j][d] = Sb[j*64 + d];
    }
    __syncthreads();

    const int tr = (tid >> 4) << 2;
    const int tc = (tid & 15) << 2;

    float acc[4][4], sca[4][4];
    #pragma unroll
    for (int i = 0; i < 4; ++i)
        #pragma unroll
        for (int j = 0; j < 4; ++j) { acc[i][j] = 0.0f; sca[i][j] = 0.0f; }

    #pragma unroll 4
    for (int dd = 0; dd < 64; ++dd) {
        float bv[4], kv[4], av[4];
        *(float4*)bv = *(const float4*)&Bs[dd][tc];
        *(float4*)kv = *(const float4*)&KT[dd][tc];
        #pragma unroll
        for (int i = 0; i < 4; ++i) av[i] = Qs[tr+i][dd];
        #pragma unroll
        for (int i = 0; i < 4; ++i)
            #pragma unroll
            for (int j = 0; j < 4; ++j) {
                acc[i][j] = fmaf(av[i], bv[j], acc[i][j]);
                sca[i][j] = fmaf(av[i], kv[j], sca[i][j]);
            }
    }

    #pragma unroll
    for (int i = 0; i < 4; ++i)
        #pragma unroll
        for (int j = 0; j < 4; ++j)
            Sc[tr+i][tc+j] = ((tc+j) <= (tr+i)) ? sca[i][j] : 0.0f;
    __syncthreads();

    #pragma unroll
    for (int i = 0; i < 16; ++i) {
        const int j = j0 + 4*i;
        Bs[j][d] = v[base + (size_t)j*DM + d];
    }
    __syncthreads();

    #pragma unroll 4
    for (int dd = 0; dd < 64; ++dd) {
        float bv[4], av[4];
        *(float4*)bv = *(const float4*)&Bs[dd][tc];
        #pragma unroll
        for (int i = 0; i < 4; ++i) av[i] = Sc[tr+i][dd];
        #pragma unroll
        for (int i = 0; i < 4; ++i)
            #pragma unroll
            for (int j = 0; j < 4; ++j)
                acc[i][j] = fmaf(av[i], bv[j], acc[i][j]);
    }

    #pragma unroll
    for (int i = 0; i < 4; ++i) {
        const size_t off = base + (size_t)(tr+i)*DM + tc;
        #pragma unroll
        for (int j = 0; j < 4; ++j)
            oh[off + j] = __float2bfloat16(acc[i][j]);
    }
}

// ---------------- SwiGLU fused with bf16 ----------------
__global__ void swiglu_split_kernel(const float* __restrict__ f1,
                                    const float* __restrict__ f2,
                                    __nv_bfloat16* __restrict__ gh,
                                    int n4)
{
    int i = blockIdx.x * blockDim.x + threadIdx.x;
    if (i < n4) {
        float4 a = ((const float4*)f1)[i];
        float4 b = ((const float4*)f2)[i];
        float r[4];
        r[0] = a.x / (1.0f + __expf(-a.x)) * b.x;
        r[1] = a.y / (1.0f + __expf(-a.y)) * b.y;
        r[2] = a.z / (1.0f + __expf(-a.z)) * b.z;
        r[3] = a.w / (1.0f + __expf(-a.w)) * b.w;
        #pragma unroll
        for (int j = 0; j < 4; ++j)
            gh[i*4 + j] = __float2bfloat16(r[j]);
    }
}

// ---------------- host launcher ----------------
extern "C" void kernel_launch(void* const* d_in, const int* in_sizes, int n_in,
                              void* d_out, int out_size)
{
    const float* x   = (const float*)d_in[0];
    const float* Wq  = (const float*)d_in[1];
    const float* Wk  = (const float*)d_in[2];
    const float* Wv  = (const float*)d_in[3];
    const float* Wg  = (const float*)d_in[4];
    const float* Wo  = (const float*)d_in[5];
    const float* w1  = (const float*)d_in[6];
    const float* w2  = (const float*)d_in[7];
    const float* w3  = (const float*)d_in[8];
    const float* gat = (const float*)d_in[9];
    const float* gff = (const float*)d_in[10];
    float* out = (float*)d_out;

    float *pq, *pk, *pv, *pa, *px1, *pf1, *pf2, *pP, *pSs, *pAe;
    __nv_bfloat16 *pxh, *pf1h;
    __nv_bfloat16 *pWTh, *pWoTh, *pW12Th, *pW3Th;
    cudaGetSymbolAddress((void**)&pq,  g_q);
    cudaGetSymbolAddress((void**)&pk,  g_k);
    cudaGetSymbolAddress((void**)&pv,  g_v);
    cudaGetSymbolAddress((void**)&pa,  g_a);
    cudaGetSymbolAddress((void**)&px1, g_x1);
    cudaGetSymbolAddress((void**)&pf1, g_f1);
    cudaGetSymbolAddress((void**)&pf2, g_f2);
    cudaGetSymbolAddress((void**)&pP,  g_P);
    cudaGetSymbolAddress((void**)&pSs, g_Ss);
    cudaGetSymbolAddress((void**)&pAe, g_Ae);
    cudaGetSymbolAddress((void**)&pxh, g_xh);
    cudaGetSymbolAddress((void**)&pf1h, g_f1h);
    cudaGetSymbolAddress((void**)&pWTh, g_WTh);
    cudaGetSymbolAddress((void**)&pWoTh, g_WoTh);
    cudaGetSymbolAddress((void**)&pW12Th, g_W12Th);
    cudaGetSymbolAddress((void**)&pW3Th, g_W3Th);

    static bool attr_done = false;
    if (!attr_done) {
        cudaFuncSetAttribute(chunk_output_kernel,
                             cudaFuncAttributeMaxDynamicSharedMemorySize,
                             4 * 64 * PAD * (int)sizeof(float));
        cudaFuncSetAttribute(bfgemm_kernel<1>,
                             cudaFuncAttributeMaxDynamicSharedMemorySize,
                             GEMM_SMEM1);
        attr_done = true;
    }

    dim3 tb(32, 8);
    // 0) transpose weights to bf16 (hi only — all GEMMs single-term now)
    transpose_split_kernel<<<dim3(32, 32), tb>>>(Wq, pWTh, nullptr, 1024, 1024, 1024, 0);
    transpose_split_kernel<<<dim3(32, 32), tb>>>(Wk, pWTh, nullptr, 1024, 1024, 1024, 1024);
    transpose_split_kernel<<<dim3(32, 32), tb>>>(Wv, pWTh, nullptr, 1024, 1024, 1024, 2048);
    transpose_split_kernel<<<dim3(32, 32), tb>>>(Wg, pWTh, nullptr, 1024, 1024, 1024, 3072);
    transpose_split_kernel<<<dim3(32, 32), tb>>>(Wo, pWoTh, nullptr, 1024, 1024, 1024, 0);
    transpose_split_kernel<<<dim3(32, DFFP/32), tb>>>(w1, pW12Th, nullptr, 1024, DFF, 1024, 0);
    transpose_split_kernel<<<dim3(32, DFFP/32), tb>>>(w2, pW12Th, nullptr, 1024, DFF, 1024, DFFP);
    transpose_split_kernel<<<dim3(DFFP/32, 32), tb>>>(w3, pW3Th, nullptr, DFF, 1024, DFFP, 0);

    // 1) h = rmsnorm(x, g_attn) -> bf16
    rmsnorm_split_kernel<<<BT, 256>>>(x, gat, pxh, nullptr);

    // 2) q,k,v,gate = h @ {Wq,Wk,Wv,Wg}  (single bf16, one N=4096 GEMM)
    bfgemm_kernel<1><<<dim3(4096/128, BT/128), 256, GEMM_SMEM1>>>(
        pxh, nullptr, pWTh, nullptr, pq, pk, pv, pa, nullptr, 1024, 1024);

    // 3) l2norm(q), l2norm(k), log-sigmoid(gate)
    qknorm_kernel<<<BT, 256>>>(pq, pk, pa);

    // 4) chunked GLA -> o (bf16)
    chunk_summary_kernel<<<NBHC, 256>>>(pq, pk, pv, pa, pP, pAe);
    chunk_state_kernel  <<<32,   256>>>(pP, pAe, pSs);
    chunk_output_kernel <<<NBHC, 256, 4*64*PAD*(int)sizeof(float)>>>(pq, pk, pv, pSs, pxh);

    // 5) x1 = x + o @ Wo   (single bf16)
    bfgemm_kernel<1><<<dim3(1024/128, BT/128), 256, GEMM_SMEM1>>>(
        pxh, nullptr, pWoTh, nullptr, px1, nullptr, nullptr, nullptr, x, 1024, 1024);

    // 6) h = rmsnorm(x1, g_ffn) -> bf16
    rmsnorm_split_kernel<<<BT, 256>>>(px1, gff, pxh, nullptr);

    // 7) f1 = h @ w1 ; f2 = h @ w2   (single bf16, one N=5632 GEMM)
    bfgemm_kernel<1><<<dim3(2*DFFP/128, BT/128), 256, GEMM_SMEM1>>>(
        pxh, nullptr, pW12Th, nullptr, pf1, pf2, nullptr, nullptr, nullptr, 1024, DFFP);

    // 8) gated = silu(f1) * f2 -> bf16
    {
        const int n4 = BT * DFFP / 4;
        swiglu_split_kernel<<<(n4 + 255)/256, 256>>>(pf1, pf2, pf1h, n4);
    }

    // 9) out = x1 + gated @ w3  (single bf16, K = 2816 padded)
    bfgemm_kernel<1><<<dim3(1024/128, BT/128), 256, GEMM_SMEM1>>>(
        pf1h, nullptr, pW3Th, nullptr, out, nullptr, nullptr, nullptr, px1, DFFP, 1024);
}